// round 1
// baseline (speedup 1.0000x reference)
#include <cuda_runtime.h>
#include <math.h>

// Problem constants
#define NNODES 30000
#define VDIM   4

// Per-warp fused evaluation of the full chain for one (node, v) task.
// Lane-distributed register layouts:
//   y1    : o = 32*m + lane,   m in [0,8)   (256 outputs)
//   basis : o = 4*lane + m,    m in [0,4)   (128 outputs)
//   h     : o = 128*j + 4*lane + m, j in {0,1}, m in [0,4)  (256 outputs)
__global__ __launch_bounds__(128, 4)
void solcalc_surface_kernel(
    const float* __restrict__ centers,      // (N,3)
    const float* __restrict__ enc_g,        // (N,64)
    const float* __restrict__ enc_n,        // (N,128)
    const float* __restrict__ nbrs,         // (N,6,3)
    const float* __restrict__ normals,      // (N,3)
    const float* __restrict__ nbr_normals,  // (N,6,3)
    const float* __restrict__ areas,        // (N,1)
    const float* __restrict__ nbr_areas,    // (N,6,1)
    const float* __restrict__ W1,           // (4,7,256)
    const float* __restrict__ b1,           // (4,256)
    const float* __restrict__ W2,           // (4,256,128)
    const float* __restrict__ b2,           // (4,128)
    const float* __restrict__ A1,           // (4,320,256)  rows: [0,128)=A1b, [128,256)=A1n, [256,320)=A1g
    const float* __restrict__ Ab1,          // (4,256)
    const float* __restrict__ A2,           // (4,256,1)
    const float* __restrict__ Ab2,          // (4,1)
    float* __restrict__ out)                // (N,4)
{
    const int warp = threadIdx.x >> 5;
    const int l    = threadIdx.x & 31;
    const int t    = blockIdx.x * 4 + warp;     // 120000 tasks
    const int v    = t / NNODES;                // blocks-per-v = 7500 exactly
    const int n    = t % NNODES;

    __shared__ float xs_all[4][7][8];
    __shared__ float inv_all[4][8];
    float (*xs)[8] = xs_all[warp];
    float* invs    = inv_all[warp];

    // ---- Build the 7 input points (7 dims each) ----
    if (l < 7) {
        if (l == 0) {
            xs[0][0] = centers[n*3+0];
            xs[0][1] = centers[n*3+1];
            xs[0][2] = centers[n*3+2];
            xs[0][3] = normals[n*3+0];
            xs[0][4] = normals[n*3+1];
            xs[0][5] = normals[n*3+2];
            xs[0][6] = logf(areas[n]) * 0.1f;
        } else {
            const int s = l - 1;
            const int base = (n*6 + s) * 3;
            xs[l][0] = nbrs[base+0]        + 1e-6f;
            xs[l][1] = nbrs[base+1]        + 1e-6f;
            xs[l][2] = nbrs[base+2]        + 1e-6f;
            xs[l][3] = nbr_normals[base+0] + 1e-6f;
            xs[l][4] = nbr_normals[base+1] + 1e-6f;
            xs[l][5] = nbr_normals[base+2] + 1e-6f;
            xs[l][6] = logf(nbr_areas[n*6 + s]) * 0.1f + 1e-6f;
        }
    }
    __syncwarp();

    // ---- 1/dist for the 6 neighbors ----
    if (l >= 1 && l < 7) {
        float d2 = 0.f;
        #pragma unroll
        for (int k = 0; k < 7; k++) {
            float d = xs[0][k] - xs[l][k];
            d2 += d * d;
        }
        invs[l-1] = 1.0f / sqrtf(d2);
    }
    __syncwarp();

    const float* A1v = A1 + v * 320 * 256;

    // ---- enc_pre[o] = enc_n @ A1n + enc_g @ A1g + Ab1   (o = 128*j + 4l + m) ----
    float en[4], eg[2];
    #pragma unroll
    for (int m = 0; m < 4; m++) en[m] = enc_n[n*128 + 32*m + l];
    #pragma unroll
    for (int m = 0; m < 2; m++) eg[m] = enc_g[n*64 + 32*m + l];

    float accE[2][4];
    {
        float4 a0 = *(const float4*)(Ab1 + v*256 + 4*l);
        float4 a1 = *(const float4*)(Ab1 + v*256 + 128 + 4*l);
        accE[0][0]=a0.x; accE[0][1]=a0.y; accE[0][2]=a0.z; accE[0][3]=a0.w;
        accE[1][0]=a1.x; accE[1][1]=a1.y; accE[1][2]=a1.z; accE[1][3]=a1.w;
    }
    #pragma unroll
    for (int m = 0; m < 4; m++) {
        #pragma unroll 4
        for (int kk = 0; kk < 32; kk++) {
            const int k = 32*m + kk;
            const float bnk = __shfl_sync(0xffffffffu, en[m], kk);
            const float* row = A1v + (128 + k) * 256;
            float4 w0 = *(const float4*)(row + 4*l);
            float4 w1 = *(const float4*)(row + 128 + 4*l);
            accE[0][0] += bnk*w0.x; accE[0][1] += bnk*w0.y; accE[0][2] += bnk*w0.z; accE[0][3] += bnk*w0.w;
            accE[1][0] += bnk*w1.x; accE[1][1] += bnk*w1.y; accE[1][2] += bnk*w1.z; accE[1][3] += bnk*w1.w;
        }
    }
    #pragma unroll
    for (int m = 0; m < 2; m++) {
        #pragma unroll 4
        for (int kk = 0; kk < 32; kk++) {
            const int k = 32*m + kk;
            const float bgk = __shfl_sync(0xffffffffu, eg[m], kk);
            const float* row = A1v + (256 + k) * 256;
            float4 w0 = *(const float4*)(row + 4*l);
            float4 w1 = *(const float4*)(row + 128 + 4*l);
            accE[0][0] += bgk*w0.x; accE[0][1] += bgk*w0.y; accE[0][2] += bgk*w0.z; accE[0][3] += bgk*w0.w;
            accE[1][0] += bgk*w1.x; accE[1][1] += bgk*w1.y; accE[1][2] += bgk*w1.z; accE[1][3] += bgk*w1.w;
        }
    }

    // ---- Layer 1: y1[p][o] = relu(x[p] @ W1 + b1),  o = 32*m + l ----
    float y[7][8];
    {
        const float* W1v = W1 + v * 7 * 256;
        const float* b1v = b1 + v * 256;
        #pragma unroll
        for (int m = 0; m < 8; m++) {
            const float bb = b1v[32*m + l];
            #pragma unroll
            for (int p = 0; p < 7; p++) y[p][m] = bb;
        }
        #pragma unroll
        for (int k = 0; k < 7; k++) {
            float xk[7];
            #pragma unroll
            for (int p = 0; p < 7; p++) xk[p] = xs[p][k];
            #pragma unroll
            for (int m = 0; m < 8; m++) {
                const float w = W1v[k*256 + 32*m + l];
                #pragma unroll
                for (int p = 0; p < 7; p++) y[p][m] += xk[p] * w;
            }
        }
        #pragma unroll
        for (int p = 0; p < 7; p++)
            #pragma unroll
            for (int m = 0; m < 8; m++) y[p][m] = fmaxf(y[p][m], 0.f);
    }

    // ---- Layer 2: basis[p][o] = y1[p] @ W2 + b2,  o = 4*l + m ----
    float acc2[7][4];
    {
        float4 bb = *(const float4*)(b2 + v*128 + 4*l);
        #pragma unroll
        for (int p = 0; p < 7; p++) {
            acc2[p][0]=bb.x; acc2[p][1]=bb.y; acc2[p][2]=bb.z; acc2[p][3]=bb.w;
        }
    }
    {
        const float* W2v = W2 + v * 256 * 128;
        #pragma unroll
        for (int m = 0; m < 8; m++) {
            #pragma unroll 2
            for (int kk = 0; kk < 32; kk++) {
                const int k = 32*m + kk;
                float4 w = *(const float4*)(W2v + k*128 + 4*l);
                #pragma unroll
                for (int p = 0; p < 7; p++) {
                    const float yk = __shfl_sync(0xffffffffu, y[p][m], kk);
                    acc2[p][0] += yk*w.x; acc2[p][1] += yk*w.y;
                    acc2[p][2] += yk*w.z; acc2[p][3] += yk*w.w;
                }
            }
        }
    }

    // ---- Layer 3: h[p][o] = relu(basis[p] @ A1b + enc_pre),  o = 128*j + 4*l + m ----
    float acc3[7][2][4];
    #pragma unroll
    for (int p = 0; p < 7; p++)
        #pragma unroll
        for (int j = 0; j < 2; j++)
            #pragma unroll
            for (int m = 0; m < 4; m++) acc3[p][j][m] = accE[j][m];

    #pragma unroll
    for (int m = 0; m < 4; m++) {
        #pragma unroll 2
        for (int q = 0; q < 32; q++) {
            const int k = 4*q + m;                  // basis index owned by lane q, reg m
            const float* row = A1v + k * 256;       // A1b rows [0,128)
            float4 w0 = *(const float4*)(row + 4*l);
            float4 w1 = *(const float4*)(row + 128 + 4*l);
            #pragma unroll
            for (int p = 0; p < 7; p++) {
                const float bk = __shfl_sync(0xffffffffu, acc2[p][m], q);
                acc3[p][0][0] += bk*w0.x; acc3[p][0][1] += bk*w0.y;
                acc3[p][0][2] += bk*w0.z; acc3[p][0][3] += bk*w0.w;
                acc3[p][1][0] += bk*w1.x; acc3[p][1][1] += bk*w1.y;
                acc3[p][1][2] += bk*w1.z; acc3[p][1][3] += bk*w1.w;
            }
        }
    }

    // ---- Layer 4: out[p] = relu(h) . A2 ----
    float4 a20 = *(const float4*)(A2 + v*256 + 4*l);
    float4 a21 = *(const float4*)(A2 + v*256 + 128 + 4*l);
    float outp[7];
    #pragma unroll
    for (int p = 0; p < 7; p++) {
        float s = 0.f;
        s += fmaxf(acc3[p][0][0], 0.f)*a20.x;
        s += fmaxf(acc3[p][0][1], 0.f)*a20.y;
        s += fmaxf(acc3[p][0][2], 0.f)*a20.z;
        s += fmaxf(acc3[p][0][3], 0.f)*a20.w;
        s += fmaxf(acc3[p][1][0], 0.f)*a21.x;
        s += fmaxf(acc3[p][1][1], 0.f)*a21.y;
        s += fmaxf(acc3[p][1][2], 0.f)*a21.z;
        s += fmaxf(acc3[p][1][3], 0.f)*a21.w;
        outp[p] = s;
    }
    #pragma unroll
    for (int off = 16; off > 0; off >>= 1) {
        #pragma unroll
        for (int p = 0; p < 7; p++)
            outp[p] += __shfl_xor_sync(0xffffffffu, outp[p], off);
    }

    // ---- Combine center + inverse-distance-weighted neighbors ----
    if (l == 0) {
        const float ab2 = Ab2[v];
        const float out_c = outp[0] + ab2;
        float num = 0.f, den = 0.f;
        #pragma unroll
        for (int s = 0; s < 6; s++) {
            const float iv = invs[s];
            num += (outp[s+1] + ab2) * iv;
            den += iv;
        }
        out[n * VDIM + v] = 0.5f * out_c + 0.5f * num / den;
    }
}

extern "C" void kernel_launch(void* const* d_in, const int* in_sizes, int n_in,
                              void* d_out, int out_size) {
    const float* centers     = (const float*)d_in[0];
    const float* enc_g       = (const float*)d_in[1];
    const float* enc_n       = (const float*)d_in[2];
    const float* nbrs        = (const float*)d_in[3];
    const float* normals     = (const float*)d_in[4];
    const float* nbr_normals = (const float*)d_in[5];
    const float* areas       = (const float*)d_in[6];
    const float* nbr_areas   = (const float*)d_in[7];
    // d_in[8], d_in[9]: global_params_* — unused by the reference math
    const float* W1  = (const float*)d_in[10];
    const float* b1  = (const float*)d_in[11];
    const float* W2  = (const float*)d_in[12];
    const float* b2  = (const float*)d_in[13];
    const float* A1  = (const float*)d_in[14];
    const float* Ab1 = (const float*)d_in[15];
    const float* A2  = (const float*)d_in[16];
    const float* Ab2 = (const float*)d_in[17];
    float* out = (float*)d_out;

    // 120000 warp-tasks, 4 warps per block -> 30000 blocks
    solcalc_surface_kernel<<<30000, 128>>>(
        centers, enc_g, enc_n, nbrs, normals, nbr_normals, areas, nbr_areas,
        W1, b1, W2, b2, A1, Ab1, A2, Ab2, out);
}

// round 2
// speedup vs baseline: 1.1458x; 1.1458x over previous
#include <cuda_runtime.h>
#include <math.h>

// Problem constants
#define NNODES 30000
#define VDIM   4

// ---- packed fp32x2 helpers (sm_100+: fma.rn.f32x2) ----
__device__ __forceinline__ void ffma2(unsigned long long &d, unsigned long long a, unsigned long long b) {
    asm("fma.rn.f32x2 %0, %1, %2, %0;" : "+l"(d) : "l"(a), "l"(b));
}
__device__ __forceinline__ unsigned long long splat2(float s) {
    unsigned long long r;
    asm("mov.b64 %0, {%1, %1};" : "=l"(r) : "f"(s));
    return r;
}
__device__ __forceinline__ unsigned long long pack2(float x, float y) {
    unsigned long long r;
    asm("mov.b64 %0, {%1, %2};" : "=l"(r) : "f"(x), "f"(y));
    return r;
}
__device__ __forceinline__ void unpack2(unsigned long long v, float &lo, float &hi) {
    asm("mov.b64 {%0, %1}, %2;" : "=f"(lo), "=f"(hi) : "l"(v));
}

// Per-warp fused evaluation of the full chain for one (node, v) task.
// Lane-distributed register layouts:
//   y1    : o = 32*m + lane,   m in [0,8)   (256 outputs)
//   basis : o = 4*lane + m,    m in [0,4)   (128 outputs)
//   h     : o = 128*j + 4*lane + m          (256 outputs)
__global__ __launch_bounds__(128, 4)
void solcalc_surface_kernel(
    const float* __restrict__ centers,      // (N,3)
    const float* __restrict__ enc_g,        // (N,64)
    const float* __restrict__ enc_n,        // (N,128)
    const float* __restrict__ nbrs,         // (N,6,3)
    const float* __restrict__ normals,      // (N,3)
    const float* __restrict__ nbr_normals,  // (N,6,3)
    const float* __restrict__ areas,        // (N,1)
    const float* __restrict__ nbr_areas,    // (N,6,1)
    const float* __restrict__ W1,           // (4,7,256)
    const float* __restrict__ b1,           // (4,256)
    const float* __restrict__ W2,           // (4,256,128)
    const float* __restrict__ b2,           // (4,128)
    const float* __restrict__ A1,           // (4,320,256)  rows: [0,128)=A1b, [128,256)=A1n, [256,320)=A1g
    const float* __restrict__ Ab1,          // (4,256)
    const float* __restrict__ A2,           // (4,256,1)
    const float* __restrict__ Ab2,          // (4,1)
    float* __restrict__ out)                // (N,4)
{
    const int warp = threadIdx.x >> 5;
    const int l    = threadIdx.x & 31;
    const int t    = blockIdx.x * 4 + warp;     // 120000 tasks
    const int v    = t / NNODES;                // blocks-per-v = 7500 exactly
    const int n    = t % NNODES;

    __shared__ float xs_all[4][7][8];
    __shared__ float inv_all[4][8];
    float (*xs)[8] = xs_all[warp];
    float* invs    = inv_all[warp];

    // ---- Build the 7 input points (7 dims each) ----
    if (l < 7) {
        if (l == 0) {
            xs[0][0] = centers[n*3+0];
            xs[0][1] = centers[n*3+1];
            xs[0][2] = centers[n*3+2];
            xs[0][3] = normals[n*3+0];
            xs[0][4] = normals[n*3+1];
            xs[0][5] = normals[n*3+2];
            xs[0][6] = logf(areas[n]) * 0.1f;
        } else {
            const int s = l - 1;
            const int base = (n*6 + s) * 3;
            xs[l][0] = nbrs[base+0]        + 1e-6f;
            xs[l][1] = nbrs[base+1]        + 1e-6f;
            xs[l][2] = nbrs[base+2]        + 1e-6f;
            xs[l][3] = nbr_normals[base+0] + 1e-6f;
            xs[l][4] = nbr_normals[base+1] + 1e-6f;
            xs[l][5] = nbr_normals[base+2] + 1e-6f;
            xs[l][6] = logf(nbr_areas[n*6 + s]) * 0.1f + 1e-6f;
        }
    }
    __syncwarp();

    // ---- 1/dist for the 6 neighbors ----
    if (l >= 1 && l < 7) {
        float d2 = 0.f;
        #pragma unroll
        for (int k = 0; k < 7; k++) {
            float d = xs[0][k] - xs[l][k];
            d2 += d * d;
        }
        invs[l-1] = 1.0f / sqrtf(d2);
    }
    __syncwarp();

    const float* A1v = A1 + v * 320 * 256;

    // ---- enc_pre[o] = enc_n @ A1n + enc_g @ A1g + Ab1 ----
    // accEp[j][h] : j selects o-halves [0,128)/[128,256), h selects float-pair
    // within the lane's 4 outputs (o = 128*j + 4*l + 2*h + {0,1})
    float en[4], eg[2];
    #pragma unroll
    for (int m = 0; m < 4; m++) en[m] = enc_n[n*128 + 32*m + l];
    #pragma unroll
    for (int m = 0; m < 2; m++) eg[m] = enc_g[n*64 + 32*m + l];

    unsigned long long accEp[2][2];
    {
        float4 a0 = *(const float4*)(Ab1 + v*256 + 4*l);
        float4 a1 = *(const float4*)(Ab1 + v*256 + 128 + 4*l);
        accEp[0][0] = pack2(a0.x, a0.y); accEp[0][1] = pack2(a0.z, a0.w);
        accEp[1][0] = pack2(a1.x, a1.y); accEp[1][1] = pack2(a1.z, a1.w);
    }
    #pragma unroll
    for (int m = 0; m < 4; m++) {
        #pragma unroll 4
        for (int kk = 0; kk < 32; kk++) {
            const int k = 32*m + kk;
            const unsigned long long s = splat2(__shfl_sync(0xffffffffu, en[m], kk));
            const float* row = A1v + (128 + k) * 256;
            ulonglong2 w0 = *(const ulonglong2*)(row + 4*l);
            ulonglong2 w1 = *(const ulonglong2*)(row + 128 + 4*l);
            ffma2(accEp[0][0], w0.x, s); ffma2(accEp[0][1], w0.y, s);
            ffma2(accEp[1][0], w1.x, s); ffma2(accEp[1][1], w1.y, s);
        }
    }
    #pragma unroll
    for (int m = 0; m < 2; m++) {
        #pragma unroll 4
        for (int kk = 0; kk < 32; kk++) {
            const int k = 32*m + kk;
            const unsigned long long s = splat2(__shfl_sync(0xffffffffu, eg[m], kk));
            const float* row = A1v + (256 + k) * 256;
            ulonglong2 w0 = *(const ulonglong2*)(row + 4*l);
            ulonglong2 w1 = *(const ulonglong2*)(row + 128 + 4*l);
            ffma2(accEp[0][0], w0.x, s); ffma2(accEp[0][1], w0.y, s);
            ffma2(accEp[1][0], w1.x, s); ffma2(accEp[1][1], w1.y, s);
        }
    }

    // ---- Layer 1: y1[p][o] = relu(x[p] @ W1 + b1),  o = 32*m + l ----
    float y[7][8];
    {
        const float* W1v = W1 + v * 7 * 256;
        const float* b1v = b1 + v * 256;
        #pragma unroll
        for (int m = 0; m < 8; m++) {
            const float bb = b1v[32*m + l];
            #pragma unroll
            for (int p = 0; p < 7; p++) y[p][m] = bb;
        }
        #pragma unroll
        for (int k = 0; k < 7; k++) {
            float xk[7];
            #pragma unroll
            for (int p = 0; p < 7; p++) xk[p] = xs[p][k];
            #pragma unroll
            for (int m = 0; m < 8; m++) {
                const float w = W1v[k*256 + 32*m + l];
                #pragma unroll
                for (int p = 0; p < 7; p++) y[p][m] += xk[p] * w;
            }
        }
        #pragma unroll
        for (int p = 0; p < 7; p++)
            #pragma unroll
            for (int m = 0; m < 8; m++) y[p][m] = fmaxf(y[p][m], 0.f);
    }

    // ---- Layer 2: basis[p][o] = y1[p] @ W2 + b2,  o = 4*l + 2*h + {0,1} ----
    unsigned long long acc2p[7][2];
    {
        float4 bb = *(const float4*)(b2 + v*128 + 4*l);
        const unsigned long long blo = pack2(bb.x, bb.y);
        const unsigned long long bhi = pack2(bb.z, bb.w);
        #pragma unroll
        for (int p = 0; p < 7; p++) { acc2p[p][0] = blo; acc2p[p][1] = bhi; }
    }
    {
        const float* W2v = W2 + v * 256 * 128;
        #pragma unroll
        for (int m = 0; m < 8; m++) {
            #pragma unroll 2
            for (int kk = 0; kk < 32; kk++) {
                const int k = 32*m + kk;
                ulonglong2 w = *(const ulonglong2*)(W2v + k*128 + 4*l);
                #pragma unroll
                for (int p = 0; p < 7; p++) {
                    const unsigned long long s = splat2(__shfl_sync(0xffffffffu, y[p][m], kk));
                    ffma2(acc2p[p][0], w.x, s);
                    ffma2(acc2p[p][1], w.y, s);
                }
            }
        }
    }

    // unpack basis to scalars for the layer-3 broadcast
    float acc2[7][4];
    #pragma unroll
    for (int p = 0; p < 7; p++) {
        unpack2(acc2p[p][0], acc2[p][0], acc2[p][1]);
        unpack2(acc2p[p][1], acc2[p][2], acc2[p][3]);
    }

    // ---- Layer 3: h[p][o] = relu(basis[p] @ A1b + enc_pre) ----
    unsigned long long acc3p[7][2][2];
    #pragma unroll
    for (int p = 0; p < 7; p++)
        #pragma unroll
        for (int j = 0; j < 2; j++) {
            acc3p[p][j][0] = accEp[j][0];
            acc3p[p][j][1] = accEp[j][1];
        }

    #pragma unroll
    for (int m = 0; m < 4; m++) {
        #pragma unroll 2
        for (int q = 0; q < 32; q++) {
            const int k = 4*q + m;                  // basis index owned by lane q, reg m
            const float* row = A1v + k * 256;       // A1b rows [0,128)
            ulonglong2 w0 = *(const ulonglong2*)(row + 4*l);
            ulonglong2 w1 = *(const ulonglong2*)(row + 128 + 4*l);
            #pragma unroll
            for (int p = 0; p < 7; p++) {
                const unsigned long long s = splat2(__shfl_sync(0xffffffffu, acc2[p][m], q));
                ffma2(acc3p[p][0][0], w0.x, s); ffma2(acc3p[p][0][1], w0.y, s);
                ffma2(acc3p[p][1][0], w1.x, s); ffma2(acc3p[p][1][1], w1.y, s);
            }
        }
    }

    // ---- Layer 4: out[p] = relu(h) . A2 ----
    float4 a20 = *(const float4*)(A2 + v*256 + 4*l);
    float4 a21 = *(const float4*)(A2 + v*256 + 128 + 4*l);
    float outp[7];
    #pragma unroll
    for (int p = 0; p < 7; p++) {
        float h0, h1, h2, h3, h4, h5, h6, h7;
        unpack2(acc3p[p][0][0], h0, h1);
        unpack2(acc3p[p][0][1], h2, h3);
        unpack2(acc3p[p][1][0], h4, h5);
        unpack2(acc3p[p][1][1], h6, h7);
        float s = 0.f;
        s += fmaxf(h0, 0.f)*a20.x;
        s += fmaxf(h1, 0.f)*a20.y;
        s += fmaxf(h2, 0.f)*a20.z;
        s += fmaxf(h3, 0.f)*a20.w;
        s += fmaxf(h4, 0.f)*a21.x;
        s += fmaxf(h5, 0.f)*a21.y;
        s += fmaxf(h6, 0.f)*a21.z;
        s += fmaxf(h7, 0.f)*a21.w;
        outp[p] = s;
    }
    #pragma unroll
    for (int off = 16; off > 0; off >>= 1) {
        #pragma unroll
        for (int p = 0; p < 7; p++)
            outp[p] += __shfl_xor_sync(0xffffffffu, outp[p], off);
    }

    // ---- Combine center + inverse-distance-weighted neighbors ----
    if (l == 0) {
        const float ab2 = Ab2[v];
        const float out_c = outp[0] + ab2;
        float num = 0.f, den = 0.f;
        #pragma unroll
        for (int s = 0; s < 6; s++) {
            const float iv = invs[s];
            num += (outp[s+1] + ab2) * iv;
            den += iv;
        }
        out[n * VDIM + v] = 0.5f * out_c + 0.5f * num / den;
    }
}

extern "C" void kernel_launch(void* const* d_in, const int* in_sizes, int n_in,
                              void* d_out, int out_size) {
    const float* centers     = (const float*)d_in[0];
    const float* enc_g       = (const float*)d_in[1];
    const float* enc_n       = (const float*)d_in[2];
    const float* nbrs        = (const float*)d_in[3];
    const float* normals     = (const float*)d_in[4];
    const float* nbr_normals = (const float*)d_in[5];
    const float* areas       = (const float*)d_in[6];
    const float* nbr_areas   = (const float*)d_in[7];
    // d_in[8], d_in[9]: global_params_* — unused by the reference math
    const float* W1  = (const float*)d_in[10];
    const float* b1  = (const float*)d_in[11];
    const float* W2  = (const float*)d_in[12];
    const float* b2  = (const float*)d_in[13];
    const float* A1  = (const float*)d_in[14];
    const float* Ab1 = (const float*)d_in[15];
    const float* A2  = (const float*)d_in[16];
    const float* Ab2 = (const float*)d_in[17];
    float* out = (float*)d_out;

    // 120000 warp-tasks, 4 warps per block -> 30000 blocks
    solcalc_surface_kernel<<<30000, 128>>>(
        centers, enc_g, enc_n, nbrs, normals, nbr_normals, areas, nbr_areas,
        W1, b1, W2, b2, A1, Ab1, A2, Ab2, out);
}

// round 4
// speedup vs baseline: 1.6500x; 1.4401x over previous
#include <cuda_runtime.h>
#include <cuda_bf16.h>
#include <stdint.h>
#include <math.h>

#define NNODES 30000
#define VDIM   4
#define NODES_PER_BLK 16
#define NBLKS  (NNODES / NODES_PER_BLK)   // 1875
#define THREADS 256

// ---- shared memory layout (bytes) ----
#define SMB_HI 0          // B chunk hi: 128 rows x 144B (pitch 72 halves)
#define SMB_LO 18432      // B chunk lo
#define SM_XS  36864      // 128*8 floats
#define SM_W1  40960      // 7*256 floats
#define SM_B1  48128      // 256 floats
#define SM_B2  49152      // 128 floats
#define SM_AB1 49664      // 256 floats
#define SM_A2  50688      // 256 floats
#define SM_INV 51712      // 96 floats
#define SM_VAL 52224      // 128 floats
#define SM_TOTAL 52736

// ---- pre-split weights / encodings (filled by prep kernel each launch) ----
__device__ __nv_bfloat16 g_W2T_hi[4 * 128 * 256];   // [v][o][k] = W2[v][k][o]
__device__ __nv_bfloat16 g_W2T_lo[4 * 128 * 256];
__device__ __nv_bfloat16 g_A1T_hi[4 * 256 * 320];   // [v][o][k] = A1[v][k][o]
__device__ __nv_bfloat16 g_A1T_lo[4 * 256 * 320];
__device__ uint32_t      g_encP_hi[NNODES * 96];    // packed bf16 pairs, k-major
__device__ uint32_t      g_encP_lo[NNODES * 96];

// ---- helpers ----
__device__ __forceinline__ void split2(float f0, float f1, uint32_t &h, uint32_t &l) {
    __nv_bfloat16 h0 = __float2bfloat16(f0), h1 = __float2bfloat16(f1);
    float r0 = f0 - __bfloat162float(h0), r1 = f1 - __bfloat162float(h1);
    __nv_bfloat16 l0 = __float2bfloat16(r0), l1 = __float2bfloat16(r1);
    h = (uint32_t)__bfloat16_as_ushort(h0) | ((uint32_t)__bfloat16_as_ushort(h1) << 16);
    l = (uint32_t)__bfloat16_as_ushort(l0) | ((uint32_t)__bfloat16_as_ushort(l1) << 16);
}

__device__ __forceinline__ void mma16816(float* c,
                                         uint32_t a0, uint32_t a1, uint32_t a2, uint32_t a3,
                                         uint32_t b0, uint32_t b1) {
    asm volatile(
        "mma.sync.aligned.m16n8k16.row.col.f32.bf16.bf16.f32 "
        "{%0,%1,%2,%3}, {%4,%5,%6,%7}, {%8,%9}, {%0,%1,%2,%3};"
        : "+f"(c[0]), "+f"(c[1]), "+f"(c[2]), "+f"(c[3])
        : "r"(a0), "r"(a1), "r"(a2), "r"(a3), "r"(b0), "r"(b1));
}

// ---- prep kernel: transpose+split W2/A1, pack+split encodings ----
__global__ void prep_kernel(const float* __restrict__ W2, const float* __restrict__ A1,
                            const float* __restrict__ enc_n, const float* __restrict__ enc_g) {
    const int n1 = 4 * 128 * 256;
    const int n2 = 4 * 256 * 320;
    const int n3 = NNODES * 96;
    for (int i = blockIdx.x * blockDim.x + threadIdx.x; i < n1 + n2 + n3;
         i += gridDim.x * blockDim.x) {
        if (i < n1) {
            int v = i / (128 * 256), rem = i % (128 * 256);
            int o = rem / 256, k = rem % 256;
            float x = W2[(v * 256 + k) * 128 + o];
            __nv_bfloat16 h = __float2bfloat16(x);
            g_W2T_hi[i] = h;
            g_W2T_lo[i] = __float2bfloat16(x - __bfloat162float(h));
        } else if (i < n1 + n2) {
            int j = i - n1;
            int v = j / (256 * 320), rem = j % (256 * 320);
            int o = rem / 320, k = rem % 320;
            float x = A1[(v * 320 + k) * 256 + o];
            __nv_bfloat16 h = __float2bfloat16(x);
            g_A1T_hi[j] = h;
            g_A1T_lo[j] = __float2bfloat16(x - __bfloat162float(h));
        } else {
            int j = i - n1 - n2;
            int n = j / 96, k2 = j % 96;
            float e0, e1;
            if (k2 < 64) { e0 = enc_n[n*128 + 2*k2];       e1 = enc_n[n*128 + 2*k2 + 1]; }
            else         { e0 = enc_g[n*64 + 2*(k2-64)];   e1 = enc_g[n*64 + 2*(k2-64) + 1]; }
            uint32_t h, l;
            split2(e0, e1, h, l);
            g_encP_hi[j] = h;
            g_encP_lo[j] = l;
        }
    }
}

// ---- main kernel ----
__global__ __launch_bounds__(THREADS)
void solcalc_mma_kernel(
    const float* __restrict__ centers, const float* __restrict__ nbrs,
    const float* __restrict__ normals, const float* __restrict__ nbr_normals,
    const float* __restrict__ areas, const float* __restrict__ nbr_areas,
    const float* __restrict__ W1, const float* __restrict__ b1,
    const float* __restrict__ b2, const float* __restrict__ Ab1,
    const float* __restrict__ A2, const float* __restrict__ Ab2,
    float* __restrict__ out)
{
    extern __shared__ char smem[];
    float* xs   = (float*)(smem + SM_XS);
    float* W1s  = (float*)(smem + SM_W1);
    float* b1s  = (float*)(smem + SM_B1);
    float* b2s  = (float*)(smem + SM_B2);
    float* Ab1s = (float*)(smem + SM_AB1);
    float* A2s  = (float*)(smem + SM_A2);
    float* inv  = (float*)(smem + SM_INV);
    float* val  = (float*)(smem + SM_VAL);

    const int tid  = threadIdx.x;
    const int wid  = tid >> 5;
    const int lane = tid & 31;
    const int g    = lane >> 2;   // 0..7
    const int t    = lane & 3;    // 0..3
    const int vb   = blockIdx.y;
    const int node0 = blockIdx.x * NODES_PER_BLK;

    // ---- stage weights / biases into SMEM ----
    for (int i = tid; i < 7 * 256; i += THREADS) W1s[i] = W1[vb * 7 * 256 + i];
    for (int i = tid; i < 256; i += THREADS) {
        b1s[i]  = b1[vb * 256 + i];
        Ab1s[i] = Ab1[vb * 256 + i];
        A2s[i]  = A2[vb * 256 + i];
    }
    if (tid < 128) b2s[tid] = b2[vb * 128 + tid];

    // ---- inputs: 7 dims per point (slot 7 = pad) ----
    if (tid < 128) {
        int r = tid, i = r >> 3, p = r & 7, n = node0 + i;
        float x[8];
#pragma unroll
        for (int d = 0; d < 8; d++) x[d] = 0.f;
        if (p == 0) {
            x[0] = centers[n*3+0]; x[1] = centers[n*3+1]; x[2] = centers[n*3+2];
            x[3] = normals[n*3+0]; x[4] = normals[n*3+1]; x[5] = normals[n*3+2];
            x[6] = logf(areas[n]) * 0.1f;
        } else if (p < 7) {
            int s = p - 1, base = (n*6 + s) * 3;
            x[0] = nbrs[base+0] + 1e-6f; x[1] = nbrs[base+1] + 1e-6f; x[2] = nbrs[base+2] + 1e-6f;
            x[3] = nbr_normals[base+0] + 1e-6f; x[4] = nbr_normals[base+1] + 1e-6f;
            x[5] = nbr_normals[base+2] + 1e-6f;
            x[6] = logf(nbr_areas[n*6 + s]) * 0.1f + 1e-6f;
        }
#pragma unroll
        for (int d = 0; d < 8; d++) xs[r*8 + d] = x[d];
    }
    __syncthreads();

    if (tid < 128) {
        int i = tid >> 3, p = tid & 7;
        if (p >= 1 && p < 7) {
            float d2 = 0.f;
#pragma unroll
            for (int d = 0; d < 7; d++) {
                float df = xs[(i*8)*8 + d] - xs[(i*8 + p)*8 + d];
                d2 += df * df;
            }
            inv[i*6 + (p-1)] = 1.0f / sqrtf(d2);
        }
    }

    // per-lane rows for this warp's m16 stripe
    const int r0 = 16*wid + g;
    const int r1 = r0 + 8;
    float xr0[7], xr1[7];
#pragma unroll
    for (int d = 0; d < 7; d++) { xr0[d] = xs[r0*8 + d]; xr1[d] = xs[r1*8 + d]; }

    // ================= LAYER 2: D2[128x128] = Y[128x256] @ W2 =================
    float acc[16][4];
#pragma unroll
    for (int nt = 0; nt < 16; nt++)
#pragma unroll
        for (int q = 0; q < 4; q++) acc[nt][q] = 0.f;

#pragma unroll
    for (int kc = 0; kc < 4; kc++) {
        __syncthreads();   // previous chunk's B reads done
        // fill B chunk: W2T rows [0,128), k-window [kc*64, +64)
        for (int idx = tid; idx < 1024; idx += THREADS) {
            int n = idx >> 3, u = idx & 7;
            long s = (long)(vb*128 + n) * 256 + kc*64 + u*8;
            *(uint4*)(smem + SMB_HI + n*144 + u*16) = *(const uint4*)(g_W2T_hi + s);
            *(uint4*)(smem + SMB_LO + n*144 + u*16) = *(const uint4*)(g_W2T_lo + s);
        }
        __syncthreads();

#pragma unroll
        for (int s = 0; s < 4; s++) {
            const int k0 = (kc*4 + s)*16 + 2*t;   // global Y column
            // layer-1: 8 Y values for this fragment
            float2 bA = *(const float2*)&b1s[k0];
            float2 bB = *(const float2*)&b1s[k0 + 8];
            float y00 = bA.x, y01 = bA.y, y10 = bA.x, y11 = bA.y;
            float y02 = bB.x, y03 = bB.y, y12 = bB.x, y13 = bB.y;
#pragma unroll
            for (int d = 0; d < 7; d++) {
                float2 wA = *(const float2*)&W1s[d*256 + k0];
                float2 wB = *(const float2*)&W1s[d*256 + k0 + 8];
                y00 += xr0[d]*wA.x; y01 += xr0[d]*wA.y;
                y10 += xr1[d]*wA.x; y11 += xr1[d]*wA.y;
                y02 += xr0[d]*wB.x; y03 += xr0[d]*wB.y;
                y12 += xr1[d]*wB.x; y13 += xr1[d]*wB.y;
            }
            uint32_t aH0,aH1,aH2,aH3, aL0,aL1,aL2,aL3;
            split2(fmaxf(y00,0.f), fmaxf(y01,0.f), aH0, aL0);
            split2(fmaxf(y10,0.f), fmaxf(y11,0.f), aH1, aL1);
            split2(fmaxf(y02,0.f), fmaxf(y03,0.f), aH2, aL2);
            split2(fmaxf(y12,0.f), fmaxf(y13,0.f), aH3, aL3);

#pragma unroll
            for (int nt = 0; nt < 16; nt++) {
                const char* bp = smem + (nt*8 + g)*144 + s*32 + t*4;
                uint32_t bh0 = *(const uint32_t*)(bp + SMB_HI);
                uint32_t bh1 = *(const uint32_t*)(bp + SMB_HI + 16);
                uint32_t bl0 = *(const uint32_t*)(bp + SMB_LO);
                uint32_t bl1 = *(const uint32_t*)(bp + SMB_LO + 16);
                mma16816(acc[nt], aH0,aH1,aH2,aH3, bh0,bh1);
                mma16816(acc[nt], aL0,aL1,aL2,aL3, bh0,bh1);
                mma16816(acc[nt], aH0,aH1,aH2,aH3, bl0,bl1);
            }
        }
    }

    // ---- convert D2 -> layer-3 A fragments (basis), add b2 ----
    uint32_t basH[8][4], basL[8][4];
#pragma unroll
    for (int s = 0; s < 8; s++) {
        float2 bb0 = *(const float2*)&b2s[16*s + 2*t];
        float2 bb1 = *(const float2*)&b2s[16*s + 8 + 2*t];
        split2(acc[2*s  ][0] + bb0.x, acc[2*s  ][1] + bb0.y, basH[s][0], basL[s][0]);
        split2(acc[2*s  ][2] + bb0.x, acc[2*s  ][3] + bb0.y, basH[s][1], basL[s][1]);
        split2(acc[2*s+1][0] + bb1.x, acc[2*s+1][1] + bb1.y, basH[s][2], basL[s][2]);
        split2(acc[2*s+1][2] + bb1.x, acc[2*s+1][3] + bb1.y, basH[s][3], basL[s][3]);
    }

    // ================= LAYER 3: D3[128x256] = [Bas|Enc] @ A1T, 2 N-passes =================
    const int n0row = node0 + 2*wid;          // node of rows g (this stripe)
    float sA = 0.f, sB = 0.f;                 // epilogue partial sums (rows r0, r1)

#pragma unroll
    for (int nh = 0; nh < 2; nh++) {
        float acc3[16][4];
#pragma unroll
        for (int nt = 0; nt < 16; nt++)
#pragma unroll
            for (int q = 0; q < 4; q++) acc3[nt][q] = 0.f;

#pragma unroll
        for (int kc = 0; kc < 5; kc++) {
            __syncthreads();
            for (int idx = tid; idx < 1024; idx += THREADS) {
                int n = idx >> 3, u = idx & 7;
                long s = (long)(vb*256 + nh*128 + n) * 320 + kc*64 + u*8;
                *(uint4*)(smem + SMB_HI + n*144 + u*16) = *(const uint4*)(g_A1T_hi + s);
                *(uint4*)(smem + SMB_LO + n*144 + u*16) = *(const uint4*)(g_A1T_lo + s);
            }
            __syncthreads();

#pragma unroll
            for (int s = 0; s < 4; s++) {
                const int ks = kc*4 + s;      // global k-step 0..19
                uint32_t aH0,aH1,aH2,aH3, aL0,aL1,aL2,aL3;
                if (ks < 8) {
                    aH0 = basH[ks][0]; aH1 = basH[ks][1]; aH2 = basH[ks][2]; aH3 = basH[ks][3];
                    aL0 = basL[ks][0]; aL1 = basL[ks][1]; aL2 = basL[ks][2]; aL3 = basL[ks][3];
                } else {
                    const int kk = ks - 8;    // enc k-step 0..11
                    const int eb = n0row*96 + 8*kk + t;
                    aH0 = g_encP_hi[eb];       aH1 = g_encP_hi[eb + 96];
                    aH2 = g_encP_hi[eb + 4];   aH3 = g_encP_hi[eb + 100];
                    aL0 = g_encP_lo[eb];       aL1 = g_encP_lo[eb + 96];
                    aL2 = g_encP_lo[eb + 4];   aL3 = g_encP_lo[eb + 100];
                }
#pragma unroll
                for (int nt = 0; nt < 16; nt++) {
                    const char* bp = smem + (nt*8 + g)*144 + s*32 + t*4;
                    uint32_t bh0 = *(const uint32_t*)(bp + SMB_HI);
                    uint32_t bh1 = *(const uint32_t*)(bp + SMB_HI + 16);
                    uint32_t bl0 = *(const uint32_t*)(bp + SMB_LO);
                    uint32_t bl1 = *(const uint32_t*)(bp + SMB_LO + 16);
                    mma16816(acc3[nt], aH0,aH1,aH2,aH3, bh0,bh1);
                    mma16816(acc3[nt], aL0,aL1,aL2,aL3, bh0,bh1);
                    mma16816(acc3[nt], aH0,aH1,aH2,aH3, bl0,bl1);
                }
            }
        }

        // ---- pass epilogue: sum relu(D3 + Ab1) * A2 over this N-half ----
#pragma unroll
        for (int nt = 0; nt < 16; nt++) {
            const int o0 = nh*128 + nt*8 + 2*t;
            float ab0 = Ab1s[o0],   a20 = A2s[o0];
            float ab1 = Ab1s[o0+1], a21 = A2s[o0+1];
            sA += fmaxf(acc3[nt][0] + ab0, 0.f)*a20 + fmaxf(acc3[nt][1] + ab1, 0.f)*a21;
            sB += fmaxf(acc3[nt][2] + ab0, 0.f)*a20 + fmaxf(acc3[nt][3] + ab1, 0.f)*a21;
        }
    }

    // reduce across the 4 t-lanes sharing a row
    sA += __shfl_xor_sync(0xffffffffu, sA, 1);
    sA += __shfl_xor_sync(0xffffffffu, sA, 2);
    sB += __shfl_xor_sync(0xffffffffu, sB, 1);
    sB += __shfl_xor_sync(0xffffffffu, sB, 2);
    if (t == 0) { val[r0] = sA; val[r1] = sB; }
    __syncthreads();

    // ---- final combine per node ----
    if (tid < NODES_PER_BLK) {
        const float ab2 = Ab2[vb];
        const int i = tid;
        float c = val[i*8] + ab2;
        float num = 0.f, den = 0.f;
#pragma unroll
        for (int s = 0; s < 6; s++) {
            float iv = inv[i*6 + s];
            num += (val[i*8 + 1 + s] + ab2) * iv;
            den += iv;
        }
        out[(node0 + i) * VDIM + vb] = 0.5f * c + 0.5f * num / den;
    }
}

extern "C" void kernel_launch(void* const* d_in, const int* in_sizes, int n_in,
                              void* d_out, int out_size) {
    const float* centers     = (const float*)d_in[0];
    const float* enc_g       = (const float*)d_in[1];
    const float* enc_n       = (const float*)d_in[2];
    const float* nbrs        = (const float*)d_in[3];
    const float* normals     = (const float*)d_in[4];
    const float* nbr_normals = (const float*)d_in[5];
    const float* areas       = (const float*)d_in[6];
    const float* nbr_areas   = (const float*)d_in[7];
    const float* W1  = (const float*)d_in[10];
    const float* b1  = (const float*)d_in[11];
    const float* W2  = (const float*)d_in[12];
    const float* b2  = (const float*)d_in[13];
    const float* A1  = (const float*)d_in[14];
    const float* Ab1 = (const float*)d_in[15];
    const float* A2  = (const float*)d_in[16];
    const float* Ab2 = (const float*)d_in[17];
    float* out = (float*)d_out;

    cudaFuncSetAttribute(solcalc_mma_kernel, cudaFuncAttributeMaxDynamicSharedMemorySize, SM_TOTAL);

    prep_kernel<<<1024, 256>>>(W2, A1, enc_n, enc_g);
    dim3 grid(NBLKS, VDIM);
    solcalc_mma_kernel<<<grid, THREADS, SM_TOTAL>>>(
        centers, nbrs, normals, nbr_normals, areas, nbr_areas,
        W1, b1, b2, Ab1, A2, Ab2, out);
}

// round 10
// speedup vs baseline: 2.6845x; 1.6270x over previous
#include <cuda_runtime.h>
#include <cuda_bf16.h>
#include <stdint.h>
#include <math.h>

#define NNODES 30000
#define VDIM   4
#define NODES_PER_BLK 16
#define NBLKS  (NNODES / NODES_PER_BLK)   // 1875
#define THREADS 256

// ---- main-kernel shared memory layout (bytes) ----
#define BUF0_HI 0
#define BUF0_LO 18432
#define BUF1_HI 36864
#define BUF1_LO 55296
#define SM_XS   73728     // 128*8 floats
#define SM_W1   77824     // 7*256 floats
#define SM_B1   84992     // 256 floats
#define SM_B2   86016     // 128 floats
#define SM_A2   86528     // 256 floats
#define SM_ENCP 87552     // 16*256 floats
#define SM_INV  103936    // 96 floats
#define SM_VAL  104320    // 128 floats
#define SM_TOTAL 104832

// ---- device scratch (prep/encpre kernels fill these every launch) ----
__device__ __nv_bfloat16 g_W2T_hi[4 * 128 * 256];   // [v][o][k] = W2[v][k][o]
__device__ __nv_bfloat16 g_W2T_lo[4 * 128 * 256];
__device__ __nv_bfloat16 g_A1T_hi[4 * 256 * 320];   // [v][o][k] = A1[v][k][o]
__device__ __nv_bfloat16 g_A1T_lo[4 * 256 * 320];
__device__ uint32_t      g_encP_hi[NNODES * 96];    // packed bf16 pairs, k-major
__device__ uint32_t      g_encP_lo[NNODES * 96];
__device__ float         g_encpre[(size_t)4 * NNODES * 256];  // enc_pre + Ab1

// ---- helpers ----
__device__ __forceinline__ void split2(float f0, float f1, uint32_t &h, uint32_t &l) {
    __nv_bfloat16 h0 = __float2bfloat16(f0), h1 = __float2bfloat16(f1);
    float r0 = f0 - __bfloat162float(h0), r1 = f1 - __bfloat162float(h1);
    __nv_bfloat16 l0 = __float2bfloat16(r0), l1 = __float2bfloat16(r1);
    h = (uint32_t)__bfloat16_as_ushort(h0) | ((uint32_t)__bfloat16_as_ushort(h1) << 16);
    l = (uint32_t)__bfloat16_as_ushort(l0) | ((uint32_t)__bfloat16_as_ushort(l1) << 16);
}

__device__ __forceinline__ void mma16816(float* c,
                                         uint32_t a0, uint32_t a1, uint32_t a2, uint32_t a3,
                                         uint32_t b0, uint32_t b1) {
    asm volatile(
        "mma.sync.aligned.m16n8k16.row.col.f32.bf16.bf16.f32 "
        "{%0,%1,%2,%3}, {%4,%5,%6,%7}, {%8,%9}, {%0,%1,%2,%3};"
        : "+f"(c[0]), "+f"(c[1]), "+f"(c[2]), "+f"(c[3])
        : "r"(a0), "r"(a1), "r"(a2), "r"(a3), "r"(b0), "r"(b1));
}

__device__ __forceinline__ uint32_t smem_u32(const void* p) {
    uint32_t a;
    asm("{ .reg .u64 t; cvta.to.shared.u64 t, %1; cvt.u32.u64 %0, t; }" : "=r"(a) : "l"(p));
    return a;
}

#define CP_ASYNC16(dst, src) asm volatile("cp.async.cg.shared.global [%0], [%1], 16;" :: "r"(dst), "l"(src))
#define CP_COMMIT() asm volatile("cp.async.commit_group;" ::: "memory")
#define CP_WAIT0() asm volatile("cp.async.wait_group 0;" ::: "memory")
#define CP_WAIT1() asm volatile("cp.async.wait_group 1;" ::: "memory")

// async fill of one B chunk (128 rows x 64 halves, hi+lo) into buffer `buf`
__device__ __forceinline__ void fill_async(uint32_t sb, int buf,
                                           const __nv_bfloat16* hi, const __nv_bfloat16* lo,
                                           long row_base, int row_len, int k0, int tid) {
    const uint32_t b_hi = sb + (buf ? BUF1_HI : BUF0_HI);
    const uint32_t b_lo = sb + (buf ? BUF1_LO : BUF0_LO);
#pragma unroll
    for (int it = 0; it < 4; it++) {
        int idx = tid + it * THREADS;
        int n = idx >> 3, u = idx & 7;
        long s = (row_base + n) * row_len + k0 + u * 8;
        uint32_t off = n * 144 + u * 16;
        CP_ASYNC16(b_hi + off, hi + s);
        CP_ASYNC16(b_lo + off, lo + s);
    }
}

// ================= prep: transpose+split W2/A1, pack+split encodings =================
__global__ void prep_kernel(const float* __restrict__ W2, const float* __restrict__ A1,
                            const float* __restrict__ enc_n, const float* __restrict__ enc_g) {
    const int n1 = 4 * 128 * 256;
    const int n2 = 4 * 256 * 320;
    const int n3 = NNODES * 96;
    for (int i = blockIdx.x * blockDim.x + threadIdx.x; i < n1 + n2 + n3;
         i += gridDim.x * blockDim.x) {
        if (i < n1) {
            int v = i / (128 * 256), rem = i % (128 * 256);
            int o = rem / 256, k = rem % 256;
            float x = W2[(v * 256 + k) * 128 + o];
            __nv_bfloat16 h = __float2bfloat16(x);
            g_W2T_hi[i] = h;
            g_W2T_lo[i] = __float2bfloat16(x - __bfloat162float(h));
        } else if (i < n1 + n2) {
            int j = i - n1;
            int v = j / (256 * 320), rem = j % (256 * 320);
            int o = rem / 320, k = rem % 320;
            float x = A1[(v * 320 + k) * 256 + o];
            __nv_bfloat16 h = __float2bfloat16(x);
            g_A1T_hi[j] = h;
            g_A1T_lo[j] = __float2bfloat16(x - __bfloat162float(h));
        } else {
            int j = i - n1 - n2;
            int n = j / 96, k2 = j % 96;
            float e0, e1;
            if (k2 < 64) { e0 = enc_n[n*128 + 2*k2];     e1 = enc_n[n*128 + 2*k2 + 1]; }
            else         { e0 = enc_g[n*64 + 2*(k2-64)]; e1 = enc_g[n*64 + 2*(k2-64) + 1]; }
            uint32_t h, l;
            split2(e0, e1, h, l);
            g_encP_hi[j] = h;
            g_encP_lo[j] = l;
        }
    }
}

// ================= encpre: g_encpre[v][n][o] = enc@A1ng + Ab1 =================
__global__ __launch_bounds__(256)
void encpre_kernel(const float* __restrict__ Ab1) {
    __shared__ char bsm[36864];     // hi at 0, lo at 18432
    const int tid  = threadIdx.x;
    const int wid  = tid >> 5;
    const int lane = tid & 31;
    const int g    = lane >> 2;
    const int t    = lane & 3;
    const int vb   = blockIdx.y;
    const int node0 = blockIdx.x * 128;

    const int nA = node0 + 16*wid + g;
    const int nB = nA + 8;
    const int nAc = nA < NNODES ? nA : NNODES - 1;
    const int nBc = nB < NNODES ? nB : NNODES - 1;

#pragma unroll
    for (int nh = 0; nh < 2; nh++) {
        float acc[16][4];
#pragma unroll
        for (int nt = 0; nt < 16; nt++)
#pragma unroll
            for (int q = 0; q < 4; q++) acc[nt][q] = 0.f;

        for (int kc = 0; kc < 3; kc++) {
            __syncthreads();
            for (int idx = tid; idx < 1024; idx += 256) {
                int n = idx >> 3, u = idx & 7;
                long s = ((long)vb*256 + nh*128 + n) * 320 + 128 + kc*64 + u*8;
                *(uint4*)(bsm + n*144 + u*16)         = *(const uint4*)(g_A1T_hi + s);
                *(uint4*)(bsm + 18432 + n*144 + u*16) = *(const uint4*)(g_A1T_lo + s);
            }
            __syncthreads();

#pragma unroll
            for (int s = 0; s < 4; s++) {
                const int ks = kc*4 + s;
                const int ebA = nAc*96 + 8*ks + t;
                const int ebB = nBc*96 + 8*ks + t;
                uint32_t aH0 = g_encP_hi[ebA],     aH1 = g_encP_hi[ebB];
                uint32_t aH2 = g_encP_hi[ebA + 4], aH3 = g_encP_hi[ebB + 4];
                uint32_t aL0 = g_encP_lo[ebA],     aL1 = g_encP_lo[ebB];
                uint32_t aL2 = g_encP_lo[ebA + 4], aL3 = g_encP_lo[ebB + 4];
#pragma unroll
                for (int nt = 0; nt < 16; nt++) {
                    const char* bp = bsm + (nt*8 + g)*144 + s*32 + t*4;
                    uint32_t bh0 = *(const uint32_t*)bp;
                    uint32_t bh1 = *(const uint32_t*)(bp + 16);
                    uint32_t bl0 = *(const uint32_t*)(bp + 18432);
                    uint32_t bl1 = *(const uint32_t*)(bp + 18432 + 16);
                    mma16816(acc[nt], aH0,aH1,aH2,aH3, bh0,bh1);
                    mma16816(acc[nt], aL0,aL1,aL2,aL3, bh0,bh1);
                    mma16816(acc[nt], aH0,aH1,aH2,aH3, bl0,bl1);
                }
            }
        }

        // epilogue: add Ab1, store fp32
#pragma unroll
        for (int nt = 0; nt < 16; nt++) {
            const int o0 = nh*128 + nt*8 + 2*t;
            float ab0 = Ab1[vb*256 + o0], ab1 = Ab1[vb*256 + o0 + 1];
            if (nA < NNODES) {
                float2 w = make_float2(acc[nt][0] + ab0, acc[nt][1] + ab1);
                *(float2*)&g_encpre[((long)vb*NNODES + nA)*256 + o0] = w;
            }
            if (nB < NNODES) {
                float2 w = make_float2(acc[nt][2] + ab0, acc[nt][3] + ab1);
                *(float2*)&g_encpre[((long)vb*NNODES + nB)*256 + o0] = w;
            }
        }
    }
}

// ================= main kernel =================
__global__ __launch_bounds__(THREADS)
void solcalc_mma_kernel(
    const float* __restrict__ centers, const float* __restrict__ nbrs,
    const float* __restrict__ normals, const float* __restrict__ nbr_normals,
    const float* __restrict__ areas, const float* __restrict__ nbr_areas,
    const float* __restrict__ W1, const float* __restrict__ b1,
    const float* __restrict__ b2, const float* __restrict__ A2,
    const float* __restrict__ Ab2,
    float* __restrict__ out)
{
    extern __shared__ char smem[];
    const uint32_t sb = smem_u32(smem);
    float* xs   = (float*)(smem + SM_XS);
    float* W1s  = (float*)(smem + SM_W1);
    float* b1s  = (float*)(smem + SM_B1);
    float* b2s  = (float*)(smem + SM_B2);
    float* A2s  = (float*)(smem + SM_A2);
    float* encp = (float*)(smem + SM_ENCP);
    float* inv  = (float*)(smem + SM_INV);
    float* val  = (float*)(smem + SM_VAL);

    const int tid  = threadIdx.x;
    const int wid  = tid >> 5;
    const int lane = tid & 31;
    const int g    = lane >> 2;
    const int t    = lane & 3;
    const int vb   = blockIdx.y;
    const int node0 = blockIdx.x * NODES_PER_BLK;

    // kick off the first W2 B-chunk prefetch immediately
    fill_async(sb, 0, g_W2T_hi, g_W2T_lo, (long)vb*128, 256, 0, tid);
    CP_COMMIT();

    // ---- stage weights / biases / enc_pre into SMEM ----
    for (int i = tid; i < 7 * 256; i += THREADS) W1s[i] = W1[vb * 7 * 256 + i];
    for (int i = tid; i < 256; i += THREADS) {
        b1s[i] = b1[vb * 256 + i];
        A2s[i] = A2[vb * 256 + i];
    }
    if (tid < 128) b2s[tid] = b2[vb * 128 + tid];
    {
        const float* src = g_encpre + ((long)vb*NNODES + node0)*256;
        for (int i = tid; i < 1024; i += THREADS)
            *(float4*)&encp[i*4] = *(const float4*)&src[i*4];
    }

    // ---- inputs: 7 dims per point (slot 7 = pad) ----
    if (tid < 128) {
        int r = tid, i = r >> 3, p = r & 7, n = node0 + i;
        float x[8];
#pragma unroll
        for (int d = 0; d < 8; d++) x[d] = 0.f;
        if (p == 0) {
            x[0] = centers[n*3+0]; x[1] = centers[n*3+1]; x[2] = centers[n*3+2];
            x[3] = normals[n*3+0]; x[4] = normals[n*3+1]; x[5] = normals[n*3+2];
            x[6] = logf(areas[n]) * 0.1f;
        } else if (p < 7) {
            int s = p - 1, base = (n*6 + s) * 3;
            x[0] = nbrs[base+0] + 1e-6f; x[1] = nbrs[base+1] + 1e-6f; x[2] = nbrs[base+2] + 1e-6f;
            x[3] = nbr_normals[base+0] + 1e-6f; x[4] = nbr_normals[base+1] + 1e-6f;
            x[5] = nbr_normals[base+2] + 1e-6f;
            x[6] = logf(nbr_areas[n*6 + s]) * 0.1f + 1e-6f;
        }
#pragma unroll
        for (int d = 0; d < 8; d++) xs[r*8 + d] = x[d];
    }
    __syncthreads();

    if (tid < 128) {
        int i = tid >> 3, p = tid & 7;
        if (p >= 1 && p < 7) {
            float d2 = 0.f;
#pragma unroll
            for (int d = 0; d < 7; d++) {
                float df = xs[(i*8)*8 + d] - xs[(i*8 + p)*8 + d];
                d2 += df * df;
            }
            inv[i*6 + (p-1)] = 1.0f / sqrtf(d2);
        }
    }

    const int r0 = 16*wid + g;
    const int r1 = r0 + 8;
    float xr0[7], xr1[7];
#pragma unroll
    for (int d = 0; d < 7; d++) { xr0[d] = xs[r0*8 + d]; xr1[d] = xs[r1*8 + d]; }

    // ================= LAYER 2: D2[128x128] = Y[128x256] @ W2 =================
    float acc[16][4];
#pragma unroll
    for (int nt = 0; nt < 16; nt++)
#pragma unroll
        for (int q = 0; q < 4; q++) acc[nt][q] = 0.f;

#pragma unroll
    for (int kc = 0; kc < 4; kc++) {
        if (kc < 3) {
            fill_async(sb, (kc+1) & 1, g_W2T_hi, g_W2T_lo, (long)vb*128, 256, (kc+1)*64, tid);
            CP_COMMIT();
            CP_WAIT1();
        } else {
            CP_WAIT0();
        }
        __syncthreads();
        const char* bufp = smem + ((kc & 1) ? BUF1_HI : BUF0_HI);

#pragma unroll
        for (int s = 0; s < 4; s++) {
            const int k0 = (kc*4 + s)*16 + 2*t;
            float2 bA = *(const float2*)&b1s[k0];
            float2 bB = *(const float2*)&b1s[k0 + 8];
            float y00 = bA.x, y01 = bA.y, y10 = bA.x, y11 = bA.y;
            float y02 = bB.x, y03 = bB.y, y12 = bB.x, y13 = bB.y;
#pragma unroll
            for (int d = 0; d < 7; d++) {
                float2 wA = *(const float2*)&W1s[d*256 + k0];
                float2 wB = *(const float2*)&W1s[d*256 + k0 + 8];
                y00 += xr0[d]*wA.x; y01 += xr0[d]*wA.y;
                y10 += xr1[d]*wA.x; y11 += xr1[d]*wA.y;
                y02 += xr0[d]*wB.x; y03 += xr0[d]*wB.y;
                y12 += xr1[d]*wB.x; y13 += xr1[d]*wB.y;
            }
            uint32_t aH0,aH1,aH2,aH3, aL0,aL1,aL2,aL3;
            split2(fmaxf(y00,0.f), fmaxf(y01,0.f), aH0, aL0);
            split2(fmaxf(y10,0.f), fmaxf(y11,0.f), aH1, aL1);
            split2(fmaxf(y02,0.f), fmaxf(y03,0.f), aH2, aL2);
            split2(fmaxf(y12,0.f), fmaxf(y13,0.f), aH3, aL3);

#pragma unroll
            for (int nt = 0; nt < 16; nt++) {
                const char* bp = bufp + (nt*8 + g)*144 + s*32 + t*4;
                uint32_t bh0 = *(const uint32_t*)bp;
                uint32_t bh1 = *(const uint32_t*)(bp + 16);
                uint32_t bl0 = *(const uint32_t*)(bp + 18432);
                uint32_t bl1 = *(const uint32_t*)(bp + 18432 + 16);
                mma16816(acc[nt], aH0,aH1,aH2,aH3, bh0,bh1);
                mma16816(acc[nt], aL0,aL1,aL2,aL3, bh0,bh1);
                mma16816(acc[nt], aH0,aH1,aH2,aH3, bl0,bl1);
            }
        }
        __syncthreads();
    }

    // ---- convert D2 -> layer-3 A fragments (basis), add b2 ----
    uint32_t basH[8][4], basL[8][4];
#pragma unroll
    for (int s = 0; s < 8; s++) {
        float2 bb0 = *(const float2*)&b2s[16*s + 2*t];
        float2 bb1 = *(const float2*)&b2s[16*s + 8 + 2*t];
        split2(acc[2*s  ][0] + bb0.x, acc[2*s  ][1] + bb0.y, basH[s][0], basL[s][0]);
        split2(acc[2*s  ][2] + bb0.x, acc[2*s  ][3] + bb0.y, basH[s][1], basL[s][1]);
        split2(acc[2*s+1][0] + bb1.x, acc[2*s+1][1] + bb1.y, basH[s][2], basL[s][2]);
        split2(acc[2*s+1][2] + bb1.x, acc[2*s+1][3] + bb1.y, basH[s][3], basL[s][3]);
    }

    // ================= LAYER 3: D3[128x256] = Bas[128x128] @ A1b, + enc_pre in epilogue =====
    float sA = 0.f, sB = 0.f;
    float acc3[16][4];

    fill_async(sb, 0, g_A1T_hi, g_A1T_lo, (long)vb*256, 320, 0, tid);
    CP_COMMIT();

#pragma unroll
    for (int cc = 0; cc < 4; cc++) {
        const int nh = cc >> 1, kc = cc & 1;
        if (kc == 0) {
#pragma unroll
            for (int nt = 0; nt < 16; nt++)
#pragma unroll
                for (int q = 0; q < 4; q++) acc3[nt][q] = 0.f;
        }
        if (cc < 3) {
            const int nn = (cc+1) >> 1, nk = (cc+1) & 1;
            fill_async(sb, (cc+1) & 1, g_A1T_hi, g_A1T_lo, (long)vb*256 + nn*128, 320, nk*64, tid);
            CP_COMMIT();
            CP_WAIT1();
        } else {
            CP_WAIT0();
        }
        __syncthreads();
        const char* bufp = smem + ((cc & 1) ? BUF1_HI : BUF0_HI);

#pragma unroll
        for (int s = 0; s < 4; s++) {
            const int ks = kc*4 + s;
            uint32_t aH0 = basH[ks][0], aH1 = basH[ks][1], aH2 = basH[ks][2], aH3 = basH[ks][3];
            uint32_t aL0 = basL[ks][0], aL1 = basL[ks][1], aL2 = basL[ks][2], aL3 = basL[ks][3];
#pragma unroll
            for (int nt = 0; nt < 16; nt++) {
                const char* bp = bufp + (nt*8 + g)*144 + s*32 + t*4;
                uint32_t bh0 = *(const uint32_t*)bp;
                uint32_t bh1 = *(const uint32_t*)(bp + 16);
                uint32_t bl0 = *(const uint32_t*)(bp + 18432);
                uint32_t bl1 = *(const uint32_t*)(bp + 18432 + 16);
                mma16816(acc3[nt], aH0,aH1,aH2,aH3, bh0,bh1);
                mma16816(acc3[nt], aL0,aL1,aL2,aL3, bh0,bh1);
                mma16816(acc3[nt], aH0,aH1,aH2,aH3, bl0,bl1);
            }
        }
        __syncthreads();

        if (kc == 1) {
            // epilogue for this N-half: sum relu(D3 + enc_pre) * A2
#pragma unroll
            for (int nt = 0; nt < 16; nt++) {
                const int o0 = nh*128 + nt*8 + 2*t;
                float2 eA = *(const float2*)&encp[(2*wid)*256 + o0];
                float2 eB = *(const float2*)&encp[(2*wid+1)*256 + o0];
                float2 a2 = *(const float2*)&A2s[o0];
                sA += fmaxf(acc3[nt][0] + eA.x, 0.f)*a2.x + fmaxf(acc3[nt][1] + eA.y, 0.f)*a2.y;
                sB += fmaxf(acc3[nt][2] + eB.x, 0.f)*a2.x + fmaxf(acc3[nt][3] + eB.y, 0.f)*a2.y;
            }
        }
    }

    // reduce across the 4 t-lanes sharing a row
    sA += __shfl_xor_sync(0xffffffffu, sA, 1);
    sA += __shfl_xor_sync(0xffffffffu, sA, 2);
    sB += __shfl_xor_sync(0xffffffffu, sB, 1);
    sB += __shfl_xor_sync(0xffffffffu, sB, 2);
    if (t == 0) { val[r0] = sA; val[r1] = sB; }
    __syncthreads();

    // ---- final combine per node ----
    if (tid < NODES_PER_BLK) {
        const float ab2 = Ab2[vb];
        const int i = tid;
        float c = val[i*8] + ab2;
        float num = 0.f, den = 0.f;
#pragma unroll
        for (int s = 0; s < 6; s++) {
            float iv = inv[i*6 + s];
            num += (val[i*8 + 1 + s] + ab2) * iv;
            den += iv;
        }
        out[(node0 + i) * VDIM + vb] = 0.5f * c + 0.5f * num / den;
    }
}

extern "C" void kernel_launch(void* const* d_in, const int* in_sizes, int n_in,
                              void* d_out, int out_size) {
    const float* centers     = (const float*)d_in[0];
    const float* enc_g       = (const float*)d_in[1];
    const float* enc_n       = (const float*)d_in[2];
    const float* nbrs        = (const float*)d_in[3];
    const float* normals     = (const float*)d_in[4];
    const float* nbr_normals = (const float*)d_in[5];
    const float* areas       = (const float*)d_in[6];
    const float* nbr_areas   = (const float*)d_in[7];
    const float* W1  = (const float*)d_in[10];
    const float* b1  = (const float*)d_in[11];
    const float* W2  = (const float*)d_in[12];
    const float* b2  = (const float*)d_in[13];
    const float* A1  = (const float*)d_in[14];
    const float* Ab1 = (const float*)d_in[15];
    const float* A2  = (const float*)d_in[16];
    const float* Ab2 = (const float*)d_in[17];
    float* out = (float*)d_out;

    cudaFuncSetAttribute(solcalc_mma_kernel, cudaFuncAttributeMaxDynamicSharedMemorySize, SM_TOTAL);

    prep_kernel<<<1024, 256>>>(W2, A1, enc_n, enc_g);
    dim3 eg((NNODES + 127) / 128, VDIM);
    encpre_kernel<<<eg, 256>>>(Ab1);
    dim3 grid(NBLKS, VDIM);
    solcalc_mma_kernel<<<grid, THREADS, SM_TOTAL>>>(
        centers, nbrs, normals, nbr_normals, areas, nbr_areas,
        W1, b1, b2, A2, Ab2, out);
}

// round 12
// speedup vs baseline: 2.8505x; 1.0618x over previous
#include <cuda_runtime.h>
#include <cuda_bf16.h>
#include <stdint.h>
#include <math.h>

#define NNODES 30000
#define VDIM   4
#define NODES_PER_BLK 16
#define NBLKS  (NNODES / NODES_PER_BLK)   // 1875
#define THREADS 256

// ---- main-kernel shared memory layout (bytes) ----
#define BUF0_HI 0
#define BUF0_LO 18432
#define BUF1_HI 36864
#define BUF1_LO 55296
#define SM_XS   73728     // 128*8 floats
#define SM_W1   77824     // 7*256 floats
#define SM_B1   84992     // 256 floats
#define SM_B2   86016     // 128 floats
#define SM_A2   86528     // 256 floats
#define SM_ENCP 87552     // 16*256 floats
#define SM_INV  103936    // 96 floats
#define SM_VAL  104320    // 128 floats
#define SM_TOTAL 104832

// ---- device scratch (prep/encpre kernels fill these every launch) ----
__device__ __nv_bfloat16 g_W2T_hi[4 * 128 * 256];   // [v][o][k] = W2[v][k][o]
__device__ __nv_bfloat16 g_W2T_lo[4 * 128 * 256];
__device__ __nv_bfloat16 g_A1T_hi[4 * 256 * 320];   // [v][o][k] = A1[v][k][o]
__device__ __nv_bfloat16 g_A1T_lo[4 * 256 * 320];
__device__ uint32_t      g_encP_hi[NNODES * 96];    // packed bf16 pairs, k-major
__device__ uint32_t      g_encP_lo[NNODES * 96];
__device__ float         g_encpre[(size_t)4 * NNODES * 256];  // enc_pre + Ab1

// ---- helpers ----
__device__ __forceinline__ void split2(float f0, float f1, uint32_t &h, uint32_t &l) {
    __nv_bfloat16 h0 = __float2bfloat16(f0), h1 = __float2bfloat16(f1);
    float r0 = f0 - __bfloat162float(h0), r1 = f1 - __bfloat162float(h1);
    __nv_bfloat16 l0 = __float2bfloat16(r0), l1 = __float2bfloat16(r1);
    h = (uint32_t)__bfloat16_as_ushort(h0) | ((uint32_t)__bfloat16_as_ushort(h1) << 16);
    l = (uint32_t)__bfloat16_as_ushort(l0) | ((uint32_t)__bfloat16_as_ushort(l1) << 16);
}

__device__ __forceinline__ void mma16816(float* c,
                                         uint32_t a0, uint32_t a1, uint32_t a2, uint32_t a3,
                                         uint32_t b0, uint32_t b1) {
    asm volatile(
        "mma.sync.aligned.m16n8k16.row.col.f32.bf16.bf16.f32 "
        "{%0,%1,%2,%3}, {%4,%5,%6,%7}, {%8,%9}, {%0,%1,%2,%3};"
        : "+f"(c[0]), "+f"(c[1]), "+f"(c[2]), "+f"(c[3])
        : "r"(a0), "r"(a1), "r"(a2), "r"(a3), "r"(b0), "r"(b1));
}

__device__ __forceinline__ uint32_t smem_u32(const void* p) {
    uint32_t a;
    asm("{ .reg .u64 t; cvta.to.shared.u64 t, %1; cvt.u32.u64 %0, t; }" : "=r"(a) : "l"(p));
    return a;
}

#define CP_ASYNC16(dst, src) asm volatile("cp.async.cg.shared.global [%0], [%1], 16;" :: "r"(dst), "l"(src))
#define CP_COMMIT() asm volatile("cp.async.commit_group;" ::: "memory")
#define CP_WAIT0() asm volatile("cp.async.wait_group 0;" ::: "memory")
#define CP_WAIT1() asm volatile("cp.async.wait_group 1;" ::: "memory")

// async fill of one B chunk (128 rows x 64 halves, hi+lo) into buffer `buf`
__device__ __forceinline__ void fill_async(uint32_t sb, int buf,
                                           const __nv_bfloat16* hi, const __nv_bfloat16* lo,
                                           long row_base, int row_len, int k0, int tid) {
    const uint32_t b_hi = sb + (buf ? BUF1_HI : BUF0_HI);
    const uint32_t b_lo = sb + (buf ? BUF1_LO : BUF0_LO);
#pragma unroll
    for (int it = 0; it < 4; it++) {
        int idx = tid + it * THREADS;
        int n = idx >> 3, u = idx & 7;
        long s = (row_base + n) * row_len + k0 + u * 8;
        uint32_t off = n * 144 + u * 16;
        CP_ASYNC16(b_hi + off, hi + s);
        CP_ASYNC16(b_lo + off, lo + s);
    }
}

// ================= prep: transpose+split W2/A1, pack+split encodings =================
__global__ void prep_kernel(const float* __restrict__ W2, const float* __restrict__ A1,
                            const float* __restrict__ enc_n, const float* __restrict__ enc_g) {
    const int n1 = 4 * 128 * 256;
    const int n2 = 4 * 256 * 320;
    const int n3 = NNODES * 96;
    for (int i = blockIdx.x * blockDim.x + threadIdx.x; i < n1 + n2 + n3;
         i += gridDim.x * blockDim.x) {
        if (i < n1) {
            int v = i / (128 * 256), rem = i % (128 * 256);
            int o = rem / 256, k = rem % 256;
            float x = W2[(v * 256 + k) * 128 + o];
            __nv_bfloat16 h = __float2bfloat16(x);
            g_W2T_hi[i] = h;
            g_W2T_lo[i] = __float2bfloat16(x - __bfloat162float(h));
        } else if (i < n1 + n2) {
            int j = i - n1;
            int v = j / (256 * 320), rem = j % (256 * 320);
            int o = rem / 320, k = rem % 320;
            float x = A1[(v * 320 + k) * 256 + o];
            __nv_bfloat16 h = __float2bfloat16(x);
            g_A1T_hi[j] = h;
            g_A1T_lo[j] = __float2bfloat16(x - __bfloat162float(h));
        } else {
            int j = i - n1 - n2;
            int n = j / 96, k2 = j % 96;
            float e0, e1;
            if (k2 < 64) { e0 = enc_n[n*128 + 2*k2];     e1 = enc_n[n*128 + 2*k2 + 1]; }
            else         { e0 = enc_g[n*64 + 2*(k2-64)]; e1 = enc_g[n*64 + 2*(k2-64) + 1]; }
            uint32_t h, l;
            split2(e0, e1, h, l);
            g_encP_hi[j] = h;
            g_encP_lo[j] = l;
        }
    }
}

// ================= encpre: g_encpre[v][n][o] = enc@A1ng + Ab1 =================
__global__ __launch_bounds__(256)
void encpre_kernel(const float* __restrict__ Ab1) {
    __shared__ char bsm[36864];     // hi at 0, lo at 18432
    const int tid  = threadIdx.x;
    const int wid  = tid >> 5;
    const int lane = tid & 31;
    const int g    = lane >> 2;
    const int t    = lane & 3;
    const int vb   = blockIdx.y;
    const int node0 = blockIdx.x * 128;

    const int nA = node0 + 16*wid + g;
    const int nB = nA + 8;
    const int nAc = nA < NNODES ? nA : NNODES - 1;
    const int nBc = nB < NNODES ? nB : NNODES - 1;

#pragma unroll
    for (int nh = 0; nh < 2; nh++) {
        float acc[16][4];
#pragma unroll
        for (int nt = 0; nt < 16; nt++)
#pragma unroll
            for (int q = 0; q < 4; q++) acc[nt][q] = 0.f;

        for (int kc = 0; kc < 3; kc++) {
            __syncthreads();
            for (int idx = tid; idx < 1024; idx += 256) {
                int n = idx >> 3, u = idx & 7;
                long s = ((long)vb*256 + nh*128 + n) * 320 + 128 + kc*64 + u*8;
                *(uint4*)(bsm + n*144 + u*16)         = *(const uint4*)(g_A1T_hi + s);
                *(uint4*)(bsm + 18432 + n*144 + u*16) = *(const uint4*)(g_A1T_lo + s);
            }
            __syncthreads();

#pragma unroll
            for (int s = 0; s < 4; s++) {
                const int ks = kc*4 + s;
                const int ebA = nAc*96 + 8*ks + t;
                const int ebB = nBc*96 + 8*ks + t;
                uint32_t aH0 = g_encP_hi[ebA],     aH1 = g_encP_hi[ebB];
                uint32_t aH2 = g_encP_hi[ebA + 4], aH3 = g_encP_hi[ebB + 4];
                uint32_t aL0 = g_encP_lo[ebA],     aL1 = g_encP_lo[ebB];
                uint32_t aL2 = g_encP_lo[ebA + 4], aL3 = g_encP_lo[ebB + 4];
#pragma unroll
                for (int nt = 0; nt < 16; nt++) {
                    const char* bp = bsm + (nt*8 + g)*144 + s*32 + t*4;
                    uint32_t bh0 = *(const uint32_t*)bp;
                    uint32_t bh1 = *(const uint32_t*)(bp + 16);
                    uint32_t bl0 = *(const uint32_t*)(bp + 18432);
                    uint32_t bl1 = *(const uint32_t*)(bp + 18432 + 16);
                    mma16816(acc[nt], aH0,aH1,aH2,aH3, bh0,bh1);
                    mma16816(acc[nt], aL0,aL1,aL2,aL3, bh0,bh1);
                    mma16816(acc[nt], aH0,aH1,aH2,aH3, bl0,bl1);
                }
            }
        }

        // epilogue: add Ab1, store fp32
#pragma unroll
        for (int nt = 0; nt < 16; nt++) {
            const int o0 = nh*128 + nt*8 + 2*t;
            float ab0 = Ab1[vb*256 + o0], ab1 = Ab1[vb*256 + o0 + 1];
            if (nA < NNODES) {
                float2 w = make_float2(acc[nt][0] + ab0, acc[nt][1] + ab1);
                *(float2*)&g_encpre[((long)vb*NNODES + nA)*256 + o0] = w;
            }
            if (nB < NNODES) {
                float2 w = make_float2(acc[nt][2] + ab0, acc[nt][3] + ab1);
                *(float2*)&g_encpre[((long)vb*NNODES + nB)*256 + o0] = w;
            }
        }
    }
}

// ================= main kernel =================
__global__ __launch_bounds__(THREADS, 2)
void solcalc_mma_kernel(
    const float* __restrict__ centers, const float* __restrict__ nbrs,
    const float* __restrict__ normals, const float* __restrict__ nbr_normals,
    const float* __restrict__ areas, const float* __restrict__ nbr_areas,
    const float* __restrict__ W1, const float* __restrict__ b1,
    const float* __restrict__ b2, const float* __restrict__ A2,
    const float* __restrict__ Ab2,
    float* __restrict__ out)
{
    extern __shared__ char smem[];
    const uint32_t sb = smem_u32(smem);
    float* xs   = (float*)(smem + SM_XS);
    float* W1s  = (float*)(smem + SM_W1);
    float* b1s  = (float*)(smem + SM_B1);
    float* b2s  = (float*)(smem + SM_B2);
    float* A2s  = (float*)(smem + SM_A2);
    float* encp = (float*)(smem + SM_ENCP);
    float* inv  = (float*)(smem + SM_INV);
    float* val  = (float*)(smem + SM_VAL);

    const int tid  = threadIdx.x;
    const int wid  = tid >> 5;
    const int lane = tid & 31;
    const int g    = lane >> 2;
    const int t    = lane & 3;
    const int vb   = blockIdx.y;
    const int node0 = blockIdx.x * NODES_PER_BLK;

    // kick off the first W2 B-chunk prefetch immediately
    fill_async(sb, 0, g_W2T_hi, g_W2T_lo, (long)vb*128, 256, 0, tid);
    CP_COMMIT();

    // ---- stage weights / biases / enc_pre into SMEM ----
    for (int i = tid; i < 7 * 256; i += THREADS) W1s[i] = W1[vb * 7 * 256 + i];
    for (int i = tid; i < 256; i += THREADS) {
        b1s[i] = b1[vb * 256 + i];
        A2s[i] = A2[vb * 256 + i];
    }
    if (tid < 128) b2s[tid] = b2[vb * 128 + tid];
    {
        const float* src = g_encpre + ((long)vb*NNODES + node0)*256;
        for (int i = tid; i < 1024; i += THREADS)
            *(float4*)&encp[i*4] = *(const float4*)&src[i*4];
    }

    // ---- inputs: 7 dims per point (slot 7 = pad) ----
    if (tid < 128) {
        int r = tid, i = r >> 3, p = r & 7, n = node0 + i;
        float x[8];
#pragma unroll
        for (int d = 0; d < 8; d++) x[d] = 0.f;
        if (p == 0) {
            x[0] = centers[n*3+0]; x[1] = centers[n*3+1]; x[2] = centers[n*3+2];
            x[3] = normals[n*3+0]; x[4] = normals[n*3+1]; x[5] = normals[n*3+2];
            x[6] = logf(areas[n]) * 0.1f;
        } else if (p < 7) {
            int s = p - 1, base = (n*6 + s) * 3;
            x[0] = nbrs[base+0] + 1e-6f; x[1] = nbrs[base+1] + 1e-6f; x[2] = nbrs[base+2] + 1e-6f;
            x[3] = nbr_normals[base+0] + 1e-6f; x[4] = nbr_normals[base+1] + 1e-6f;
            x[5] = nbr_normals[base+2] + 1e-6f;
            x[6] = logf(nbr_areas[n*6 + s]) * 0.1f + 1e-6f;
        }
#pragma unroll
        for (int d = 0; d < 8; d++) xs[r*8 + d] = x[d];
    }
    __syncthreads();

    if (tid < 128) {
        int i = tid >> 3, p = tid & 7;
        if (p >= 1 && p < 7) {
            float d2 = 0.f;
#pragma unroll
            for (int d = 0; d < 7; d++) {
                float df = xs[(i*8)*8 + d] - xs[(i*8 + p)*8 + d];
                d2 += df * df;
            }
            inv[i*6 + (p-1)] = 1.0f / sqrtf(d2);
        }
    }

    const int r0 = 16*wid + g;
    const int r1 = r0 + 8;
    float xr0[7], xr1[7];
#pragma unroll
    for (int d = 0; d < 7; d++) { xr0[d] = xs[r0*8 + d]; xr1[d] = xs[r1*8 + d]; }

    // ================= LAYER 2: D2[128x128] = Y[128x256] @ W2 =================
    float acc[16][4];
#pragma unroll
    for (int nt = 0; nt < 16; nt++)
#pragma unroll
        for (int q = 0; q < 4; q++) acc[nt][q] = 0.f;

#pragma unroll
    for (int kc = 0; kc < 4; kc++) {
        if (kc < 3) {
            fill_async(sb, (kc+1) & 1, g_W2T_hi, g_W2T_lo, (long)vb*128, 256, (kc+1)*64, tid);
            CP_COMMIT();
            CP_WAIT1();
        } else {
            CP_WAIT0();
        }
        __syncthreads();
        const char* bufp = smem + ((kc & 1) ? BUF1_HI : BUF0_HI);

#pragma unroll
        for (int s = 0; s < 4; s++) {
            const int k0 = (kc*4 + s)*16 + 2*t;
            float2 bA = *(const float2*)&b1s[k0];
            float2 bB = *(const float2*)&b1s[k0 + 8];
            float y00 = bA.x, y01 = bA.y, y10 = bA.x, y11 = bA.y;
            float y02 = bB.x, y03 = bB.y, y12 = bB.x, y13 = bB.y;
#pragma unroll
            for (int d = 0; d < 7; d++) {
                float2 wA = *(const float2*)&W1s[d*256 + k0];
                float2 wB = *(const float2*)&W1s[d*256 + k0 + 8];
                y00 += xr0[d]*wA.x; y01 += xr0[d]*wA.y;
                y10 += xr1[d]*wA.x; y11 += xr1[d]*wA.y;
                y02 += xr0[d]*wB.x; y03 += xr0[d]*wB.y;
                y12 += xr1[d]*wB.x; y13 += xr1[d]*wB.y;
            }
            uint32_t aH0,aH1,aH2,aH3, aL0,aL1,aL2,aL3;
            split2(fmaxf(y00,0.f), fmaxf(y01,0.f), aH0, aL0);
            split2(fmaxf(y10,0.f), fmaxf(y11,0.f), aH1, aL1);
            split2(fmaxf(y02,0.f), fmaxf(y03,0.f), aH2, aL2);
            split2(fmaxf(y12,0.f), fmaxf(y13,0.f), aH3, aL3);

#pragma unroll
            for (int nt = 0; nt < 16; nt++) {
                const char* bp = bufp + (nt*8 + g)*144 + s*32 + t*4;
                uint32_t bh0 = *(const uint32_t*)bp;
                uint32_t bh1 = *(const uint32_t*)(bp + 16);
                uint32_t bl0 = *(const uint32_t*)(bp + 18432);
                uint32_t bl1 = *(const uint32_t*)(bp + 18432 + 16);
                mma16816(acc[nt], aH0,aH1,aH2,aH3, bh0,bh1);
                mma16816(acc[nt], aL0,aL1,aL2,aL3, bh0,bh1);
                mma16816(acc[nt], aH0,aH1,aH2,aH3, bl0,bl1);
            }
        }
        __syncthreads();
    }

    // ---- convert D2 -> layer-3 A fragments (basis), add b2 ----
    uint32_t basH[8][4], basL[8][4];
#pragma unroll
    for (int s = 0; s < 8; s++) {
        float2 bb0 = *(const float2*)&b2s[16*s + 2*t];
        float2 bb1 = *(const float2*)&b2s[16*s + 8 + 2*t];
        split2(acc[2*s  ][0] + bb0.x, acc[2*s  ][1] + bb0.y, basH[s][0], basL[s][0]);
        split2(acc[2*s  ][2] + bb0.x, acc[2*s  ][3] + bb0.y, basH[s][1], basL[s][1]);
        split2(acc[2*s+1][0] + bb1.x, acc[2*s+1][1] + bb1.y, basH[s][2], basL[s][2]);
        split2(acc[2*s+1][2] + bb1.x, acc[2*s+1][3] + bb1.y, basH[s][3], basL[s][3]);
    }

    // ================= LAYER 3: D3[128x256] = Bas[128x128] @ A1b, + enc_pre in epilogue =====
    float sA = 0.f, sB = 0.f;
    float acc3[16][4];

    fill_async(sb, 0, g_A1T_hi, g_A1T_lo, (long)vb*256, 320, 0, tid);
    CP_COMMIT();

#pragma unroll
    for (int cc = 0; cc < 4; cc++) {
        const int nh = cc >> 1, kc = cc & 1;
        if (kc == 0) {
#pragma unroll
            for (int nt = 0; nt < 16; nt++)
#pragma unroll
                for (int q = 0; q < 4; q++) acc3[nt][q] = 0.f;
        }
        if (cc < 3) {
            const int nn = (cc+1) >> 1, nk = (cc+1) & 1;
            fill_async(sb, (cc+1) & 1, g_A1T_hi, g_A1T_lo, (long)vb*256 + nn*128, 320, nk*64, tid);
            CP_COMMIT();
            CP_WAIT1();
        } else {
            CP_WAIT0();
        }
        __syncthreads();
        const char* bufp = smem + ((cc & 1) ? BUF1_HI : BUF0_HI);

#pragma unroll
        for (int s = 0; s < 4; s++) {
            const int ks = kc*4 + s;
            uint32_t aH0 = basH[ks][0], aH1 = basH[ks][1], aH2 = basH[ks][2], aH3 = basH[ks][3];
            uint32_t aL0 = basL[ks][0], aL1 = basL[ks][1], aL2 = basL[ks][2], aL3 = basL[ks][3];
#pragma unroll
            for (int nt = 0; nt < 16; nt++) {
                const char* bp = bufp + (nt*8 + g)*144 + s*32 + t*4;
                uint32_t bh0 = *(const uint32_t*)bp;
                uint32_t bh1 = *(const uint32_t*)(bp + 16);
                uint32_t bl0 = *(const uint32_t*)(bp + 18432);
                uint32_t bl1 = *(const uint32_t*)(bp + 18432 + 16);
                mma16816(acc3[nt], aH0,aH1,aH2,aH3, bh0,bh1);
                mma16816(acc3[nt], aL0,aL1,aL2,aL3, bh0,bh1);
                mma16816(acc3[nt], aH0,aH1,aH2,aH3, bl0,bl1);
            }
        }
        __syncthreads();

        if (kc == 1) {
            // epilogue for this N-half: sum relu(D3 + enc_pre) * A2
#pragma unroll
            for (int nt = 0; nt < 16; nt++) {
                const int o0 = nh*128 + nt*8 + 2*t;
                float2 eA = *(const float2*)&encp[(2*wid)*256 + o0];
                float2 eB = *(const float2*)&encp[(2*wid+1)*256 + o0];
                float2 a2 = *(const float2*)&A2s[o0];
                sA += fmaxf(acc3[nt][0] + eA.x, 0.f)*a2.x + fmaxf(acc3[nt][1] + eA.y, 0.f)*a2.y;
                sB += fmaxf(acc3[nt][2] + eB.x, 0.f)*a2.x + fmaxf(acc3[nt][3] + eB.y, 0.f)*a2.y;
            }
        }
    }

    // reduce across the 4 t-lanes sharing a row
    sA += __shfl_xor_sync(0xffffffffu, sA, 1);
    sA += __shfl_xor_sync(0xffffffffu, sA, 2);
    sB += __shfl_xor_sync(0xffffffffu, sB, 1);
    sB += __shfl_xor_sync(0xffffffffu, sB, 2);
    if (t == 0) { val[r0] = sA; val[r1] = sB; }
    __syncthreads();

    // ---- final combine per node ----
    if (tid < NODES_PER_BLK) {
        const float ab2 = Ab2[vb];
        const int i = tid;
        float c = val[i*8] + ab2;
        float num = 0.f, den = 0.f;
#pragma unroll
        for (int s = 0; s < 6; s++) {
            float iv = inv[i*6 + s];
            num += (val[i*8 + 1 + s] + ab2) * iv;
            den += iv;
        }
        out[(node0 + i) * VDIM + vb] = 0.5f * c + 0.5f * num / den;
    }
}

extern "C" void kernel_launch(void* const* d_in, const int* in_sizes, int n_in,
                              void* d_out, int out_size) {
    const float* centers     = (const float*)d_in[0];
    const float* enc_g       = (const float*)d_in[1];
    const float* enc_n       = (const float*)d_in[2];
    const float* nbrs        = (const float*)d_in[3];
    const float* normals     = (const float*)d_in[4];
    const float* nbr_normals = (const float*)d_in[5];
    const float* areas       = (const float*)d_in[6];
    const float* nbr_areas   = (const float*)d_in[7];
    const float* W1  = (const float*)d_in[10];
    const float* b1  = (const float*)d_in[11];
    const float* W2  = (const float*)d_in[12];
    const float* b2  = (const float*)d_in[13];
    const float* A1  = (const float*)d_in[14];
    const float* Ab1 = (const float*)d_in[15];
    const float* A2  = (const float*)d_in[16];
    const float* Ab2 = (const float*)d_in[17];
    float* out = (float*)d_out;

    cudaFuncSetAttribute(solcalc_mma_kernel, cudaFuncAttributeMaxDynamicSharedMemorySize, SM_TOTAL);

    prep_kernel<<<1024, 256>>>(W2, A1, enc_n, enc_g);
    dim3 eg((NNODES + 127) / 128, VDIM);
    encpre_kernel<<<eg, 256>>>(Ab1);
    dim3 grid(NBLKS, VDIM);
    solcalc_mma_kernel<<<grid, THREADS, SM_TOTAL>>>(
        centers, nbrs, normals, nbr_normals, areas, nbr_areas,
        W1, b1, b2, A2, Ab2, out);
}

// round 15
// speedup vs baseline: 3.9565x; 1.3880x over previous
#include <cuda_runtime.h>
#include <cuda_fp16.h>
#include <stdint.h>
#include <math.h>

#define NNODES 30000
#define VDIM   4
#define NODES_PER_BLK 16
#define NBLKS  (NNODES / NODES_PER_BLK)   // 1875
#define THREADS 256

// ---- main-kernel shared memory layout (bytes) ----
#define BUF0    0         // B chunk stage 0: 128 rows x 144B
#define BUF1    18432     // B chunk stage 1
#define SM_XS   36864     // 128*8 floats
#define SM_W1   40960     // 7*256 floats
#define SM_B1   48128     // 256 floats
#define SM_B2   49152     // 128 floats
#define SM_A2   49664     // 256 floats
#define SM_ENCP 50688     // 16*256 floats
#define SM_INV  67072     // 96 floats
#define SM_VAL  67456     // 128 floats
#define SM_TOTAL 67968

// ---- device scratch (prep/encpre kernels fill these every launch) ----
__device__ __half    g_W2T[4 * 128 * 256];   // [v][o][k] = fp16(W2[v][k][o])
__device__ __half    g_A1T[4 * 256 * 320];   // [v][o][k] = fp16(A1[v][k][o])
__device__ uint32_t  g_encP_hi[NNODES * 96]; // packed fp16 pairs (hi), k-major
__device__ uint32_t  g_encP_lo[NNODES * 96]; // packed fp16 pairs (lo)
__device__ float     g_encpre[(size_t)4 * NNODES * 256];  // enc_pre + Ab1

// ---- helpers ----
__device__ __forceinline__ void split2h(float f0, float f1, uint32_t &h, uint32_t &l) {
    __half h0 = __float2half_rn(f0), h1 = __float2half_rn(f1);
    float r0 = f0 - __half2float(h0), r1 = f1 - __half2float(h1);
    __half l0 = __float2half_rn(r0), l1 = __float2half_rn(r1);
    h = (uint32_t)__half_as_ushort(h0) | ((uint32_t)__half_as_ushort(h1) << 16);
    l = (uint32_t)__half_as_ushort(l0) | ((uint32_t)__half_as_ushort(l1) << 16);
}

__device__ __forceinline__ void mma16816(float* c,
                                         uint32_t a0, uint32_t a1, uint32_t a2, uint32_t a3,
                                         uint32_t b0, uint32_t b1) {
    asm volatile(
        "mma.sync.aligned.m16n8k16.row.col.f32.f16.f16.f32 "
        "{%0,%1,%2,%3}, {%4,%5,%6,%7}, {%8,%9}, {%0,%1,%2,%3};"
        : "+f"(c[0]), "+f"(c[1]), "+f"(c[2]), "+f"(c[3])
        : "r"(a0), "r"(a1), "r"(a2), "r"(a3), "r"(b0), "r"(b1));
}

__device__ __forceinline__ uint32_t smem_u32(const void* p) {
    uint32_t a;
    asm("{ .reg .u64 t; cvta.to.shared.u64 t, %1; cvt.u32.u64 %0, t; }" : "=r"(a) : "l"(p));
    return a;
}

#define CP_ASYNC16(dst, src) asm volatile("cp.async.cg.shared.global [%0], [%1], 16;" :: "r"(dst), "l"(src))
#define CP_COMMIT() asm volatile("cp.async.commit_group;" ::: "memory")
#define CP_WAIT0() asm volatile("cp.async.wait_group 0;" ::: "memory")
#define CP_WAIT1() asm volatile("cp.async.wait_group 1;" ::: "memory")

// async fill of one B chunk (128 rows x 64 halves) into buffer `buf`
__device__ __forceinline__ void fill_async(uint32_t sb, int buf, const __half* src,
                                           long row_base, int row_len, int k0, int tid) {
    const uint32_t b = sb + (buf ? BUF1 : BUF0);
#pragma unroll
    for (int it = 0; it < 4; it++) {
        int idx = tid + it * THREADS;
        int n = idx >> 3, u = idx & 7;
        long s = (row_base + n) * row_len + k0 + u * 8;
        CP_ASYNC16(b + n * 144 + u * 16, src + s);
    }
}

// ================= prep: transpose W2/A1 to fp16, pack+split encodings =================
__global__ void prep_kernel(const float* __restrict__ W2, const float* __restrict__ A1,
                            const float* __restrict__ enc_n, const float* __restrict__ enc_g) {
    const int n1 = 4 * 128 * 256;
    const int n2 = 4 * 256 * 320;
    const int n3 = NNODES * 96;
    for (int i = blockIdx.x * blockDim.x + threadIdx.x; i < n1 + n2 + n3;
         i += gridDim.x * blockDim.x) {
        if (i < n1) {
            int v = i / (128 * 256), rem = i % (128 * 256);
            int o = rem / 256, k = rem % 256;
            g_W2T[i] = __float2half_rn(W2[(v * 256 + k) * 128 + o]);
        } else if (i < n1 + n2) {
            int j = i - n1;
            int v = j / (256 * 320), rem = j % (256 * 320);
            int o = rem / 320, k = rem % 320;
            g_A1T[j] = __float2half_rn(A1[(v * 320 + k) * 256 + o]);
        } else {
            int j = i - n1 - n2;
            int n = j / 96, k2 = j % 96;
            float e0, e1;
            if (k2 < 64) { e0 = enc_n[n*128 + 2*k2];     e1 = enc_n[n*128 + 2*k2 + 1]; }
            else         { e0 = enc_g[n*64 + 2*(k2-64)]; e1 = enc_g[n*64 + 2*(k2-64) + 1]; }
            uint32_t h, l;
            split2h(e0, e1, h, l);
            g_encP_hi[j] = h;
            g_encP_lo[j] = l;
        }
    }
}

// ================= encpre: g_encpre[v][n][o] = enc@A1ng + Ab1 =================
__global__ __launch_bounds__(256)
void encpre_kernel(const float* __restrict__ Ab1) {
    __shared__ char bsm[18432];     // single B tile (fp16)
    const int tid  = threadIdx.x;
    const int wid  = tid >> 5;
    const int lane = tid & 31;
    const int g    = lane >> 2;
    const int t    = lane & 3;
    const int vb   = blockIdx.y;
    const int node0 = blockIdx.x * 128;

    const int nA = node0 + 16*wid + g;
    const int nB = nA + 8;
    const int nAc = nA < NNODES ? nA : NNODES - 1;
    const int nBc = nB < NNODES ? nB : NNODES - 1;

#pragma unroll
    for (int nh = 0; nh < 2; nh++) {
        float acc[16][4];
#pragma unroll
        for (int nt = 0; nt < 16; nt++)
#pragma unroll
            for (int q = 0; q < 4; q++) acc[nt][q] = 0.f;

        for (int kc = 0; kc < 3; kc++) {
            __syncthreads();
            for (int idx = tid; idx < 1024; idx += 256) {
                int n = idx >> 3, u = idx & 7;
                long s = ((long)vb*256 + nh*128 + n) * 320 + 128 + kc*64 + u*8;
                *(uint4*)(bsm + n*144 + u*16) = *(const uint4*)(g_A1T + s);
            }
            __syncthreads();

#pragma unroll
            for (int s = 0; s < 4; s++) {
                const int ks = kc*4 + s;
                const int ebA = nAc*96 + 8*ks + t;
                const int ebB = nBc*96 + 8*ks + t;
                uint32_t aH0 = g_encP_hi[ebA],     aH1 = g_encP_hi[ebB];
                uint32_t aH2 = g_encP_hi[ebA + 4], aH3 = g_encP_hi[ebB + 4];
                uint32_t aL0 = g_encP_lo[ebA],     aL1 = g_encP_lo[ebB];
                uint32_t aL2 = g_encP_lo[ebA + 4], aL3 = g_encP_lo[ebB + 4];
#pragma unroll
                for (int nt = 0; nt < 16; nt++) {
                    const char* bp = bsm + (nt*8 + g)*144 + s*32 + t*4;
                    uint32_t bh0 = *(const uint32_t*)bp;
                    uint32_t bh1 = *(const uint32_t*)(bp + 16);
                    mma16816(acc[nt], aH0,aH1,aH2,aH3, bh0,bh1);
                    mma16816(acc[nt], aL0,aL1,aL2,aL3, bh0,bh1);
                }
            }
        }

        // epilogue: add Ab1, store fp32
#pragma unroll
        for (int nt = 0; nt < 16; nt++) {
            const int o0 = nh*128 + nt*8 + 2*t;
            float ab0 = Ab1[vb*256 + o0], ab1 = Ab1[vb*256 + o0 + 1];
            if (nA < NNODES) {
                float2 w = make_float2(acc[nt][0] + ab0, acc[nt][1] + ab1);
                *(float2*)&g_encpre[((long)vb*NNODES + nA)*256 + o0] = w;
            }
            if (nB < NNODES) {
                float2 w = make_float2(acc[nt][2] + ab0, acc[nt][3] + ab1);
                *(float2*)&g_encpre[((long)vb*NNODES + nB)*256 + o0] = w;
            }
        }
    }
}

// ================= main kernel =================
__global__ __launch_bounds__(THREADS, 2)
void solcalc_mma_kernel(
    const float* __restrict__ centers, const float* __restrict__ nbrs,
    const float* __restrict__ normals, const float* __restrict__ nbr_normals,
    const float* __restrict__ areas, const float* __restrict__ nbr_areas,
    const float* __restrict__ W1, const float* __restrict__ b1,
    const float* __restrict__ b2, const float* __restrict__ A2,
    const float* __restrict__ Ab2,
    float* __restrict__ out)
{
    extern __shared__ char smem[];
    const uint32_t sb = smem_u32(smem);
    float* xs   = (float*)(smem + SM_XS);
    float* W1s  = (float*)(smem + SM_W1);
    float* b1s  = (float*)(smem + SM_B1);
    float* b2s  = (float*)(smem + SM_B2);
    float* A2s  = (float*)(smem + SM_A2);
    float* encp = (float*)(smem + SM_ENCP);
    float* inv  = (float*)(smem + SM_INV);
    float* val  = (float*)(smem + SM_VAL);

    const int tid  = threadIdx.x;
    const int wid  = tid >> 5;
    const int lane = tid & 31;
    const int g    = lane >> 2;
    const int t    = lane & 3;
    const int vb   = blockIdx.y;
    const int node0 = blockIdx.x * NODES_PER_BLK;

    // kick off the first W2 B-chunk prefetch immediately
    fill_async(sb, 0, g_W2T, (long)vb*128, 256, 0, tid);
    CP_COMMIT();

    // ---- stage weights / biases / enc_pre into SMEM ----
    for (int i = tid; i < 7 * 256; i += THREADS) W1s[i] = W1[vb * 7 * 256 + i];
    for (int i = tid; i < 256; i += THREADS) {
        b1s[i] = b1[vb * 256 + i];
        A2s[i] = A2[vb * 256 + i];
    }
    if (tid < 128) b2s[tid] = b2[vb * 128 + tid];
    {
        const float* src = g_encpre + ((long)vb*NNODES + node0)*256;
        for (int i = tid; i < 1024; i += THREADS)
            *(float4*)&encp[i*4] = *(const float4*)&src[i*4];
    }

    // ---- inputs: 7 dims per point (slot 7 = pad) ----
    if (tid < 128) {
        int r = tid, i = r >> 3, p = r & 7, n = node0 + i;
        float x[8];
#pragma unroll
        for (int d = 0; d < 8; d++) x[d] = 0.f;
        if (p == 0) {
            x[0] = centers[n*3+0]; x[1] = centers[n*3+1]; x[2] = centers[n*3+2];
            x[3] = normals[n*3+0]; x[4] = normals[n*3+1]; x[5] = normals[n*3+2];
            x[6] = logf(areas[n]) * 0.1f;
        } else if (p < 7) {
            int s = p - 1, base = (n*6 + s) * 3;
            x[0] = nbrs[base+0] + 1e-6f; x[1] = nbrs[base+1] + 1e-6f; x[2] = nbrs[base+2] + 1e-6f;
            x[3] = nbr_normals[base+0] + 1e-6f; x[4] = nbr_normals[base+1] + 1e-6f;
            x[5] = nbr_normals[base+2] + 1e-6f;
            x[6] = logf(nbr_areas[n*6 + s]) * 0.1f + 1e-6f;
        }
#pragma unroll
        for (int d = 0; d < 8; d++) xs[r*8 + d] = x[d];
    }
    __syncthreads();

    if (tid < 128) {
        int i = tid >> 3, p = tid & 7;
        if (p >= 1 && p < 7) {
            float d2 = 0.f;
#pragma unroll
            for (int d = 0; d < 7; d++) {
                float df = xs[(i*8)*8 + d] - xs[(i*8 + p)*8 + d];
                d2 += df * df;
            }
            inv[i*6 + (p-1)] = 1.0f / sqrtf(d2);
        }
    }

    const int r0 = 16*wid + g;
    const int r1 = r0 + 8;
    float xr0[7], xr1[7];
#pragma unroll
    for (int d = 0; d < 7; d++) { xr0[d] = xs[r0*8 + d]; xr1[d] = xs[r1*8 + d]; }

    // ================= LAYER 2: D2[128x128] = Y[128x256] @ W2 =================
    float acc[16][4];
#pragma unroll
    for (int nt = 0; nt < 16; nt++)
#pragma unroll
        for (int q = 0; q < 4; q++) acc[nt][q] = 0.f;

#pragma unroll
    for (int kc = 0; kc < 4; kc++) {
        if (kc < 3) {
            fill_async(sb, (kc+1) & 1, g_W2T, (long)vb*128, 256, (kc+1)*64, tid);
            CP_COMMIT();
            CP_WAIT1();
        } else {
            CP_WAIT0();
        }
        __syncthreads();
        const char* bufp = smem + ((kc & 1) ? BUF1 : BUF0);

#pragma unroll
        for (int s = 0; s < 4; s++) {
            const int k0 = (kc*4 + s)*16 + 2*t;
            float2 bA = *(const float2*)&b1s[k0];
            float2 bB = *(const float2*)&b1s[k0 + 8];
            float y00 = bA.x, y01 = bA.y, y10 = bA.x, y11 = bA.y;
            float y02 = bB.x, y03 = bB.y, y12 = bB.x, y13 = bB.y;
#pragma unroll
            for (int d = 0; d < 7; d++) {
                float2 wA = *(const float2*)&W1s[d*256 + k0];
                float2 wB = *(const float2*)&W1s[d*256 + k0 + 8];
                y00 += xr0[d]*wA.x; y01 += xr0[d]*wA.y;
                y10 += xr1[d]*wA.x; y11 += xr1[d]*wA.y;
                y02 += xr0[d]*wB.x; y03 += xr0[d]*wB.y;
                y12 += xr1[d]*wB.x; y13 += xr1[d]*wB.y;
            }
            uint32_t aH0,aH1,aH2,aH3, aL0,aL1,aL2,aL3;
            split2h(fmaxf(y00,0.f), fmaxf(y01,0.f), aH0, aL0);
            split2h(fmaxf(y10,0.f), fmaxf(y11,0.f), aH1, aL1);
            split2h(fmaxf(y02,0.f), fmaxf(y03,0.f), aH2, aL2);
            split2h(fmaxf(y12,0.f), fmaxf(y13,0.f), aH3, aL3);

#pragma unroll
            for (int nt = 0; nt < 16; nt++) {
                const char* bp = bufp + (nt*8 + g)*144 + s*32 + t*4;
                uint32_t bh0 = *(const uint32_t*)bp;
                uint32_t bh1 = *(const uint32_t*)(bp + 16);
                mma16816(acc[nt], aH0,aH1,aH2,aH3, bh0,bh1);
                mma16816(acc[nt], aL0,aL1,aL2,aL3, bh0,bh1);
            }
        }
        __syncthreads();
    }

    // ---- convert D2 -> layer-3 A fragments (basis), add b2 ----
    uint32_t basH[8][4], basL[8][4];
#pragma unroll
    for (int s = 0; s < 8; s++) {
        float2 bb0 = *(const float2*)&b2s[16*s + 2*t];
        float2 bb1 = *(const float2*)&b2s[16*s + 8 + 2*t];
        split2h(acc[2*s  ][0] + bb0.x, acc[2*s  ][1] + bb0.y, basH[s][0], basL[s][0]);
        split2h(acc[2*s  ][2] + bb0.x, acc[2*s  ][3] + bb0.y, basH[s][1], basL[s][1]);
        split2h(acc[2*s+1][0] + bb1.x, acc[2*s+1][1] + bb1.y, basH[s][2], basL[s][2]);
        split2h(acc[2*s+1][2] + bb1.x, acc[2*s+1][3] + bb1.y, basH[s][3], basL[s][3]);
    }

    // ================= LAYER 3: D3[128x256] = Bas[128x128] @ A1b, + enc_pre in epilogue =====
    float sA = 0.f, sB = 0.f;
    float acc3[16][4];

    fill_async(sb, 0, g_A1T, (long)vb*256, 320, 0, tid);
    CP_COMMIT();

#pragma unroll
    for (int cc = 0; cc < 4; cc++) {
        const int nh = cc >> 1, kc = cc & 1;
        if (kc == 0) {
#pragma unroll
            for (int nt = 0; nt < 16; nt++)
#pragma unroll
                for (int q = 0; q < 4; q++) acc3[nt][q] = 0.f;
        }
        if (cc < 3) {
            const int nn = (cc+1) >> 1, nk = (cc+1) & 1;
            fill_async(sb, (cc+1) & 1, g_A1T, (long)vb*256 + nn*128, 320, nk*64, tid);
            CP_COMMIT();
            CP_WAIT1();
        } else {
            CP_WAIT0();
        }
        __syncthreads();
        const char* bufp = smem + ((cc & 1) ? BUF1 : BUF0);

#pragma unroll
        for (int s = 0; s < 4; s++) {
            const int ks = kc*4 + s;
            uint32_t aH0 = basH[ks][0], aH1 = basH[ks][1], aH2 = basH[ks][2], aH3 = basH[ks][3];
            uint32_t aL0 = basL[ks][0], aL1 = basL[ks][1], aL2 = basL[ks][2], aL3 = basL[ks][3];
#pragma unroll
            for (int nt = 0; nt < 16; nt++) {
                const char* bp = bufp + (nt*8 + g)*144 + s*32 + t*4;
                uint32_t bh0 = *(const uint32_t*)bp;
                uint32_t bh1 = *(const uint32_t*)(bp + 16);
                mma16816(acc3[nt], aH0,aH1,aH2,aH3, bh0,bh1);
                mma16816(acc3[nt], aL0,aL1,aL2,aL3, bh0,bh1);
            }
        }
        __syncthreads();

        if (kc == 1) {
            // epilogue for this N-half: sum relu(D3 + enc_pre) * A2
#pragma unroll
            for (int nt = 0; nt < 16; nt++) {
                const int o0 = nh*128 + nt*8 + 2*t;
                float2 eA = *(const float2*)&encp[(2*wid)*256 + o0];
                float2 eB = *(const float2*)&encp[(2*wid+1)*256 + o0];
                float2 a2 = *(const float2*)&A2s[o0];
                sA += fmaxf(acc3[nt][0] + eA.x, 0.f)*a2.x + fmaxf(acc3[nt][1] + eA.y, 0.f)*a2.y;
                sB += fmaxf(acc3[nt][2] + eB.x, 0.f)*a2.x + fmaxf(acc3[nt][3] + eB.y, 0.f)*a2.y;
            }
        }
    }

    // reduce across the 4 t-lanes sharing a row
    sA += __shfl_xor_sync(0xffffffffu, sA, 1);
    sA += __shfl_xor_sync(0xffffffffu, sA, 2);
    sB += __shfl_xor_sync(0xffffffffu, sB, 1);
    sB += __shfl_xor_sync(0xffffffffu, sB, 2);
    if (t == 0) { val[r0] = sA; val[r1] = sB; }
    __syncthreads();

    // ---- final combine per node ----
    if (tid < NODES_PER_BLK) {
        const float ab2 = Ab2[vb];
        const int i = tid;
        float c = val[i*8] + ab2;
        float num = 0.f, den = 0.f;
#pragma unroll
        for (int s = 0; s < 6; s++) {
            float iv = inv[i*6 + s];
            num += (val[i*8 + 1 + s] + ab2) * iv;
            den += iv;
        }
        out[(node0 + i) * VDIM + vb] = 0.5f * c + 0.5f * num / den;
    }
}

extern "C" void kernel_launch(void* const* d_in, const int* in_sizes, int n_in,
                              void* d_out, int out_size) {
    const float* centers     = (const float*)d_in[0];
    const float* enc_g       = (const float*)d_in[1];
    const float* enc_n       = (const float*)d_in[2];
    const float* nbrs        = (const float*)d_in[3];
    const float* normals     = (const float*)d_in[4];
    const float* nbr_normals = (const float*)d_in[5];
    const float* areas       = (const float*)d_in[6];
    const float* nbr_areas   = (const float*)d_in[7];
    const float* W1  = (const float*)d_in[10];
    const float* b1  = (const float*)d_in[11];
    const float* W2  = (const float*)d_in[12];
    const float* b2  = (const float*)d_in[13];
    const float* A1  = (const float*)d_in[14];
    const float* Ab1 = (const float*)d_in[15];
    const float* A2  = (const float*)d_in[16];
    const float* Ab2 = (const float*)d_in[17];
    float* out = (float*)d_out;

    cudaFuncSetAttribute(solcalc_mma_kernel, cudaFuncAttributeMaxDynamicSharedMemorySize, SM_TOTAL);

    prep_kernel<<<1024, 256>>>(W2, A1, enc_n, enc_g);
    dim3 eg((NNODES + 127) / 128, VDIM);
    encpre_kernel<<<eg, 256>>>(Ab1);
    dim3 grid(NBLKS, VDIM);
    solcalc_mma_kernel<<<grid, THREADS, SM_TOTAL>>>(
        centers, nbrs, normals, nbr_normals, areas, nbr_areas,
        W1, b1, b2, A2, Ab2, out);
}